// round 1
// baseline (speedup 1.0000x reference)
#include <cuda_runtime.h>

#define Bn 4
#define Sn 1024
#define Hn 1024
#define NHn 16
#define HDn 64
#define SCALEF 0.125f
#define VERB_BIAS 2.0f

// ---------------- scratch (allocation-free) ----------------
__device__ float g_q[Bn*Sn*Hn];
__device__ float g_k[Bn*Sn*Hn];
__device__ float g_v[Bn*Sn*Hn];
__device__ float g_o[Bn*Sn*Hn];
__device__ float g_colb[Bn*Sn];
__device__ int   g_vt[Bn*Sn];

// ---------------- morpho preprocessing ----------------
// bias[b,i,j] = colb[b,j] + VERB_BIAS * (j == vt[b,i]); vt=-1 if no verb in row b.
__global__ void morpho_kernel(const int* __restrict__ morpho) {
    int b = blockIdx.x;
    int i = threadIdx.x;
    const int* mrow = morpho + b * Sn;
    __shared__ unsigned char isv[Sn];
    __shared__ int anyv;
    if (i == 0) anyv = 0;
    __syncthreads();
    int t = mrow[i];
    unsigned char iv = (t == 2);
    isv[i] = iv;
    if (iv) anyv = 1;
    g_colb[b*Sn + i] = (1.5f*0.5f) * (t == 0) + (1.2f*0.3f) * (t == 1);
    __syncthreads();
    int nearest = -1;
    if (anyv) {
        // argmin over |i-j| with ties -> smaller j: check i-d before i+d
        for (int d = 0; d < Sn; d++) {
            int jl = i - d;
            if (jl >= 0 && isv[jl]) { nearest = jl; break; }
            int jr = i + d;
            if (jr < Sn && isv[jr]) { nearest = jr; break; }
        }
    }
    g_vt[b*Sn + i] = nearest;
}

// ---------------- SGEMM 128x128x16, 8x8 per thread ----------------
#define GBM 128
#define GBN 128
#define GBK 16

__device__ __forceinline__ void sgemm_body(
    const float* __restrict__ A, const float* __restrict__ Bm,
    const float* __restrict__ bias, float* __restrict__ C,
    int M, int N, int K)
{
    __shared__ float As[GBK][GBM];
    __shared__ float Bs[GBK][GBN + 4];
    int tid = threadIdx.x;
    int tx = tid & 15, ty = tid >> 4;
    int r0 = blockIdx.y * GBM;
    int c0 = blockIdx.x * GBN;

    float acc[8][8];
    #pragma unroll
    for (int i = 0; i < 8; i++)
        #pragma unroll
        for (int j = 0; j < 8; j++) acc[i][j] = 0.f;

    for (int k0 = 0; k0 < K; k0 += GBK) {
        #pragma unroll
        for (int r = 0; r < 2; r++) {
            int idx = tid + 256 * r;           // 512 float4 of A tile
            int row = idx >> 2, c4 = idx & 3;
            float4 v4 = *(const float4*)(A + (size_t)(r0 + row) * K + k0 + c4 * 4);
            As[c4*4+0][row] = v4.x; As[c4*4+1][row] = v4.y;
            As[c4*4+2][row] = v4.z; As[c4*4+3][row] = v4.w;
        }
        #pragma unroll
        for (int r = 0; r < 2; r++) {
            int idx = tid + 256 * r;           // 512 float4 of B tile
            int rr = idx >> 5, c4 = idx & 31;
            float4 v4 = *(const float4*)(Bm + (size_t)(k0 + rr) * N + c0 + c4 * 4);
            *(float4*)&Bs[rr][c4 * 4] = v4;
        }
        __syncthreads();
        #pragma unroll
        for (int kk = 0; kk < GBK; kk++) {
            float a[8], bb[8];
            #pragma unroll
            for (int i = 0; i < 8; i++) a[i] = As[kk][ty * 8 + i];
            #pragma unroll
            for (int j = 0; j < 8; j++) bb[j] = Bs[kk][tx * 8 + j];
            #pragma unroll
            for (int i = 0; i < 8; i++)
                #pragma unroll
                for (int j = 0; j < 8; j++)
                    acc[i][j] += a[i] * bb[j];
        }
        __syncthreads();
    }
    #pragma unroll
    for (int i = 0; i < 8; i++) {
        int row = r0 + ty * 8 + i;
        #pragma unroll
        for (int j = 0; j < 8; j += 4) {
            int col = c0 + tx * 8 + j;
            float4 v4;
            v4.x = acc[i][j]   + bias[col];
            v4.y = acc[i][j+1] + bias[col+1];
            v4.z = acc[i][j+2] + bias[col+2];
            v4.w = acc[i][j+3] + bias[col+3];
            *(float4*)(C + (size_t)row * N + col) = v4;
        }
    }
}

__global__ void __launch_bounds__(256, 2) qkv_gemm(
    const float* __restrict__ X,
    const float* __restrict__ Wq, const float* __restrict__ bq,
    const float* __restrict__ Wk, const float* __restrict__ bk,
    const float* __restrict__ Wv, const float* __restrict__ bv)
{
    int z = blockIdx.z;
    const float* W    = (z == 0) ? Wq : (z == 1) ? Wk : Wv;
    const float* bias = (z == 0) ? bq : (z == 1) ? bk : bv;
    float* C          = (z == 0) ? g_q : (z == 1) ? g_k : g_v;
    sgemm_body(X, W, bias, C, Bn * Sn, Hn, Hn);
}

__global__ void __launch_bounds__(256, 2) out_gemm(
    const float* __restrict__ Wo, const float* __restrict__ bo,
    float* __restrict__ C)
{
    sgemm_body(g_o, Wo, bo, C, Bn * Sn, Hn, Hn);
}

// ---------------- flash attention 64x64 tiles ----------------
#define QP 65   // pad for scalar-read K/Q rows (2-way conflicts max)
#define VP 68   // pad (mult of 4) for float4 V/P access
#define SM_Q 0
#define SM_K (64 * QP)
#define SM_V (2 * 64 * QP)
#define SM_P (2 * 64 * QP + 64 * VP)
#define SM_TOTALF (2 * 64 * QP + 2 * 64 * VP)
#define SM_BYTES (SM_TOTALF * 4)

__global__ void __launch_bounds__(256) attn_kernel() {
    extern __shared__ float sm[];
    float* Qs = sm + SM_Q;
    float* Ks = sm + SM_K;
    float* Vs = sm + SM_V;
    float* Ps = sm + SM_P;

    int tid = threadIdx.x;
    int tx = tid & 15, ty = tid >> 4;   // thread (tx,ty): rows 4ty+i, cols 4tx+j
    int b = blockIdx.z, h = blockIdx.y;
    int i0 = blockIdx.x * 64;

    const float* qb  = g_q + (size_t)(b * Sn + i0) * Hn + h * HDn;
    const float* kb0 = g_k + (size_t)b * Sn * Hn + h * HDn;
    const float* vb0 = g_v + (size_t)b * Sn * Hn + h * HDn;
    const float* cbp = g_colb + b * Sn;

    // load Q tile [64 x 64]
    #pragma unroll
    for (int r = 0; r < 4; r++) {
        int idx = tid + 256 * r;                // 1024 float4
        int row = idx >> 4, c4 = idx & 15;
        float4 v4 = *(const float4*)(qb + (size_t)row * Hn + c4 * 4);
        Qs[row*QP + c4*4+0] = v4.x; Qs[row*QP + c4*4+1] = v4.y;
        Qs[row*QP + c4*4+2] = v4.z; Qs[row*QP + c4*4+3] = v4.w;
    }

    int vti[4];
    #pragma unroll
    for (int i = 0; i < 4; i++) vti[i] = g_vt[b * Sn + i0 + ty * 4 + i];

    float m[4], l[4], acc[4][4];
    #pragma unroll
    for (int i = 0; i < 4; i++) {
        m[i] = -3.0e38f; l[i] = 0.f;
        #pragma unroll
        for (int j = 0; j < 4; j++) acc[i][j] = 0.f;
    }

    for (int jt = 0; jt < Sn / 64; jt++) {
        int j0 = jt * 64;
        __syncthreads();
        // load K, V tiles
        #pragma unroll
        for (int r = 0; r < 4; r++) {
            int idx = tid + 256 * r;
            int row = idx >> 4, c4 = idx & 15;
            float4 kv4 = *(const float4*)(kb0 + (size_t)(j0 + row) * Hn + c4 * 4);
            Ks[row*QP + c4*4+0] = kv4.x; Ks[row*QP + c4*4+1] = kv4.y;
            Ks[row*QP + c4*4+2] = kv4.z; Ks[row*QP + c4*4+3] = kv4.w;
            float4 vv4 = *(const float4*)(vb0 + (size_t)(j0 + row) * Hn + c4 * 4);
            *(float4*)&Vs[row * VP + c4 * 4] = vv4;
        }
        __syncthreads();

        // scores S = Q K^T  (4x4 per thread)
        float s[4][4];
        #pragma unroll
        for (int i = 0; i < 4; i++)
            #pragma unroll
            for (int j = 0; j < 4; j++) s[i][j] = 0.f;
        #pragma unroll 8
        for (int d = 0; d < 64; d++) {
            float qv[4], kv[4];
            #pragma unroll
            for (int i = 0; i < 4; i++) qv[i] = Qs[(ty*4+i)*QP + d];
            #pragma unroll
            for (int j = 0; j < 4; j++) kv[j] = Ks[(tx*4+j)*QP + d];
            #pragma unroll
            for (int i = 0; i < 4; i++)
                #pragma unroll
                for (int j = 0; j < 4; j++)
                    s[i][j] += qv[i] * kv[j];
        }

        // scale + morpho bias
        float cbj[4];
        #pragma unroll
        for (int j = 0; j < 4; j++) cbj[j] = cbp[j0 + tx * 4 + j];
        #pragma unroll
        for (int i = 0; i < 4; i++)
            #pragma unroll
            for (int j = 0; j < 4; j++) {
                float val = s[i][j] * SCALEF + cbj[j];
                if (j0 + tx * 4 + j == vti[i]) val += VERB_BIAS;
                s[i][j] = val;
            }

        // online softmax (row groups = 16 lanes of same ty, width-16 shfl)
        #pragma unroll
        for (int i = 0; i < 4; i++) {
            float rm = fmaxf(fmaxf(s[i][0], s[i][1]), fmaxf(s[i][2], s[i][3]));
            #pragma unroll
            for (int off = 8; off >= 1; off >>= 1)
                rm = fmaxf(rm, __shfl_xor_sync(0xffffffffu, rm, off, 16));
            float mn = fmaxf(m[i], rm);
            float corr = __expf(m[i] - mn);
            m[i] = mn;
            float p0 = __expf(s[i][0] - mn);
            float p1 = __expf(s[i][1] - mn);
            float p2 = __expf(s[i][2] - mn);
            float p3 = __expf(s[i][3] - mn);
            float sum = (p0 + p1) + (p2 + p3);
            #pragma unroll
            for (int off = 8; off >= 1; off >>= 1)
                sum += __shfl_xor_sync(0xffffffffu, sum, off, 16);
            l[i] = l[i] * corr + sum;
            #pragma unroll
            for (int j = 0; j < 4; j++) acc[i][j] *= corr;
            float4 pw = make_float4(p0, p1, p2, p3);
            *(float4*)&Ps[(ty * 4 + i) * VP + tx * 4] = pw;
        }
        __syncwarp();

        // O += P V   (Ps rows owned/written/read by same half-warp)
        #pragma unroll 4
        for (int jj = 0; jj < 64; jj++) {
            float pv[4];
            #pragma unroll
            for (int i = 0; i < 4; i++) pv[i] = Ps[(ty * 4 + i) * VP + jj];
            float4 vv = *(const float4*)&Vs[jj * VP + tx * 4];
            #pragma unroll
            for (int i = 0; i < 4; i++) {
                acc[i][0] += pv[i] * vv.x;
                acc[i][1] += pv[i] * vv.y;
                acc[i][2] += pv[i] * vv.z;
                acc[i][3] += pv[i] * vv.w;
            }
        }
    }

    // epilogue: normalize + store
    float* ob = g_o + (size_t)(b * Sn + i0) * Hn + h * HDn;
    #pragma unroll
    for (int i = 0; i < 4; i++) {
        float inv = 1.f / l[i];
        float4 v4;
        v4.x = acc[i][0] * inv; v4.y = acc[i][1] * inv;
        v4.z = acc[i][2] * inv; v4.w = acc[i][3] * inv;
        *(float4*)(ob + (size_t)(ty * 4 + i) * Hn + tx * 4) = v4;
    }
}

// ---------------- launch ----------------
extern "C" void kernel_launch(void* const* d_in, const int* in_sizes, int n_in,
                              void* d_out, int out_size) {
    const float* hidden = (const float*)d_in[0];
    const int*   morpho = (const int*)d_in[1];
    const float* Wq = (const float*)d_in[2];
    const float* bq = (const float*)d_in[3];
    const float* Wk = (const float*)d_in[4];
    const float* bk = (const float*)d_in[5];
    const float* Wv = (const float*)d_in[6];
    const float* bv = (const float*)d_in[7];
    const float* Wo = (const float*)d_in[8];
    const float* bo = (const float*)d_in[9];
    float* out = (float*)d_out;

    cudaFuncSetAttribute(attn_kernel,
                         cudaFuncAttributeMaxDynamicSharedMemorySize, SM_BYTES);

    morpho_kernel<<<Bn, Sn>>>(morpho);
    qkv_gemm<<<dim3(Hn / GBN, (Bn * Sn) / GBM, 3), 256>>>(hidden, Wq, bq, Wk, bk, Wv, bv);
    attn_kernel<<<dim3(Sn / 64, NHn, Bn), 256, SM_BYTES>>>();
    out_gemm<<<dim3(Hn / GBN, (Bn * Sn) / GBM), 256>>>(Wo, bo, out);
}

// round 6
// speedup vs baseline: 1.5627x; 1.5627x over previous
#include <cuda_runtime.h>
#include <cuda_bf16.h>
#include <cstdint>

#define Bn 4
#define Sn 1024
#define Hn 1024
#define NHn 16
#define HDn 64
#define SCALEF 0.125f
#define VERB_BIAS 2.0f

#define Mtot (Bn*Sn)     // 4096
#define W_ELEMS (Hn*Hn)  // 1048576

// ---------------- scratch (allocation-free) ----------------
__device__ float g_q[Bn*Sn*Hn];
__device__ float g_k[Bn*Sn*Hn];
__device__ float g_v[Bn*Sn*Hn];
__device__ float g_o[Bn*Sn*Hn];
__device__ float g_colb[Bn*Sn];
__device__ int   g_vt[Bn*Sn];

// bf16 split operands
__device__ __nv_bfloat16 g_xhi[Mtot*Hn];
__device__ __nv_bfloat16 g_xlo[Mtot*Hn];
__device__ __nv_bfloat16 g_ohi[Mtot*Hn];
__device__ __nv_bfloat16 g_olo[Mtot*Hn];
__device__ __nv_bfloat16 g_wthi[4*W_ELEMS];   // W^T per matrix: [n][k]
__device__ __nv_bfloat16 g_wtlo[4*W_ELEMS];

// ---------------- warp-mma helpers (family-portable PTX only) ----------------
__device__ __forceinline__ uint32_t smem_to_u32(const void* p) {
    uint32_t a;
    asm("{ .reg .u64 t; cvta.to.shared.u64 t, %1; cvt.u32.u64 %0, t; }" : "=r"(a) : "l"(p));
    return a;
}

__device__ __forceinline__ void ldsm_x4(uint32_t addr, uint32_t& r0, uint32_t& r1,
                                        uint32_t& r2, uint32_t& r3) {
    asm volatile("ldmatrix.sync.aligned.m8n8.x4.shared.b16 {%0,%1,%2,%3}, [%4];"
        : "=r"(r0), "=r"(r1), "=r"(r2), "=r"(r3) : "r"(addr));
}

__device__ __forceinline__ void mma16816(float* c, uint32_t a0, uint32_t a1,
                                         uint32_t a2, uint32_t a3,
                                         uint32_t b0, uint32_t b1) {
    asm volatile(
        "mma.sync.aligned.m16n8k16.row.col.f32.bf16.bf16.f32 "
        "{%0,%1,%2,%3}, {%4,%5,%6,%7}, {%8,%9}, {%0,%1,%2,%3};"
        : "+f"(c[0]), "+f"(c[1]), "+f"(c[2]), "+f"(c[3])
        : "r"(a0), "r"(a1), "r"(a2), "r"(a3), "r"(b0), "r"(b1));
}

// SW128 swizzled address within a [rows x 64 bf16] tile (128B rows)
__device__ __forceinline__ uint32_t swz(uint32_t base, int row, int kb) {
    uint32_t bo = (uint32_t)(row * 128 + kb);
    return base + (bo ^ ((bo >> 3) & 0x70));
}

// ---------------- morpho preprocessing ----------------
__global__ void morpho_kernel(const int* __restrict__ morpho) {
    int b = blockIdx.x;
    int i = threadIdx.x;
    const int* mrow = morpho + b * Sn;
    __shared__ unsigned char isv[Sn];
    __shared__ int anyv;
    if (i == 0) anyv = 0;
    __syncthreads();
    int t = mrow[i];
    unsigned char iv = (t == 2);
    isv[i] = iv;
    if (iv) anyv = 1;
    g_colb[b*Sn + i] = (1.5f*0.5f) * (t == 0) + (1.2f*0.3f) * (t == 1);
    __syncthreads();
    int nearest = -1;
    if (anyv) {
        for (int d = 0; d < Sn; d++) {
            int jl = i - d;
            if (jl >= 0 && isv[jl]) { nearest = jl; break; }
            int jr = i + d;
            if (jr < Sn && isv[jr]) { nearest = jr; break; }
        }
    }
    g_vt[b*Sn + i] = nearest;
}

// ---------------- conversion kernels ----------------
__global__ void convert_split(const float* __restrict__ src,
                              __nv_bfloat16* __restrict__ hi,
                              __nv_bfloat16* __restrict__ lo, int n) {
    int idx = blockIdx.x * blockDim.x + threadIdx.x;
    idx *= 4;
    if (idx < n) {
        float4 x = *(const float4*)(src + idx);
        __nv_bfloat16 h0 = __float2bfloat16_rn(x.x);
        __nv_bfloat16 h1 = __float2bfloat16_rn(x.y);
        __nv_bfloat16 h2 = __float2bfloat16_rn(x.z);
        __nv_bfloat16 h3 = __float2bfloat16_rn(x.w);
        __nv_bfloat162 hp0, hp1, lp0, lp1;
        hp0.x = h0; hp0.y = h1; hp1.x = h2; hp1.y = h3;
        lp0.x = __float2bfloat16_rn(x.x - __bfloat162float(h0));
        lp0.y = __float2bfloat16_rn(x.y - __bfloat162float(h1));
        lp1.x = __float2bfloat16_rn(x.z - __bfloat162float(h2));
        lp1.y = __float2bfloat16_rn(x.w - __bfloat162float(h3));
        *(__nv_bfloat162*)(hi + idx) = hp0;
        *(__nv_bfloat162*)(hi + idx + 2) = hp1;
        *(__nv_bfloat162*)(lo + idx) = lp0;
        *(__nv_bfloat162*)(lo + idx + 2) = lp1;
    }
}

// transpose W [K,N] -> W^T [N,K] + bf16 split. block (32,8), grid (32,32,4)
__global__ void transpose_convert_w(const float* __restrict__ Wq, const float* __restrict__ Wk,
                                    const float* __restrict__ Wv, const float* __restrict__ Wo) {
    __shared__ float t[32][33];
    int z = blockIdx.z;
    const float* W = (z == 0) ? Wq : (z == 1) ? Wk : (z == 2) ? Wv : Wo;
    __nv_bfloat16* whi = g_wthi + (size_t)z * W_ELEMS;
    __nv_bfloat16* wlo = g_wtlo + (size_t)z * W_ELEMS;
    int n0 = blockIdx.x * 32, k0 = blockIdx.y * 32;
    int tx = threadIdx.x, ty = threadIdx.y;
    #pragma unroll
    for (int i = 0; i < 4; i++) {
        int kr = ty + i * 8;
        t[kr][tx] = W[(size_t)(k0 + kr) * Hn + n0 + tx];
    }
    __syncthreads();
    #pragma unroll
    for (int i = 0; i < 4; i++) {
        int nr = ty + i * 8;
        float x = t[tx][nr];
        __nv_bfloat16 h = __float2bfloat16_rn(x);
        whi[(size_t)(n0 + nr) * Hn + k0 + tx] = h;
        wlo[(size_t)(n0 + nr) * Hn + k0 + tx] = __float2bfloat16_rn(x - __bfloat162float(h));
    }
}

// ---------------- mma.sync GEMM: C[4096,1024] = A @ B^T + bias ----------------
// A: [M,K] bf16 hi/lo, B: W^T [N,K] bf16 hi/lo. 128x128 CTA tile, K-chunks of 64.
// 8 warps: 2(m) x 4(n); warp tile 64x32; mma m16n8k16; 3 passes (hi*hi+hi*lo+lo*hi).

#define GT_TILE 16384
#define GT_SMEM_BYTES (4*GT_TILE)   // 65536
#define NCHUNK 16

__device__ __forceinline__ void gemm_mma_body(
    const __nv_bfloat16* __restrict__ Ahi, const __nv_bfloat16* __restrict__ Alo,
    const __nv_bfloat16* __restrict__ Bhi, const __nv_bfloat16* __restrict__ Blo,
    const float* __restrict__ bias, float* __restrict__ C)
{
    extern __shared__ char sm[];
    uint32_t smb = smem_to_u32(sm);
    const uint32_t tAhi = smb;
    const uint32_t tAlo = smb + GT_TILE;
    const uint32_t tBhi = smb + 2*GT_TILE;
    const uint32_t tBlo = smb + 3*GT_TILE;

    int tid = threadIdx.x;
    int wid = tid >> 5, lane = tid & 31;
    int r0 = blockIdx.y * 128;
    int c0 = blockIdx.x * 128;

    int wm = (wid >> 2) * 64;   // warp m offset in tile
    int wn = (wid & 3) * 32;    // warp n offset in tile

    // per-lane ldmatrix addressing offsets
    int la = lane & 7, qa = lane >> 3;
    int rowoff_a = (qa & 1) * 8 + la;   // A: quads 0,1 = m halves; 2,3 = k+8
    int kboff_a  = (qa >> 1) * 16;
    int rowoff_b = (qa >> 1) * 8 + la;  // B: quads 0,1 = k halves; 2,3 = n+8
    int kboff_b  = (qa & 1) * 16;

    float acc[4][4][4];
    #pragma unroll
    for (int mf = 0; mf < 4; mf++)
        #pragma unroll
        for (int nf = 0; nf < 4; nf++)
            #pragma unroll
            for (int j = 0; j < 4; j++) acc[mf][nf][j] = 0.f;

    for (int ch = 0; ch < NCHUNK; ch++) {
        int k0 = ch * 64;
        // cooperative load of 4 tiles: [128 rows x 64 bf16] each, SW128 swizzled
        #pragma unroll
        for (int r = 0; r < 4; r++) {
            int idx = tid + 256 * r;
            int row = idx >> 3, c16 = idx & 7;
            uint32_t bo = (uint32_t)(row * 128 + c16 * 16);
            uint32_t sw = bo ^ ((bo >> 3) & 0x70);
            size_t ga = (size_t)(r0 + row) * Hn + k0 + c16 * 8;
            size_t gb = (size_t)(c0 + row) * Hn + k0 + c16 * 8;
            *(uint4*)(sm + sw)               = *(const uint4*)(Ahi + ga);
            *(uint4*)(sm + GT_TILE + sw)     = *(const uint4*)(Alo + ga);
            *(uint4*)(sm + 2*GT_TILE + sw)   = *(const uint4*)(Bhi + gb);
            *(uint4*)(sm + 3*GT_TILE + sw)   = *(const uint4*)(Blo + gb);
        }
        __syncthreads();

        #pragma unroll
        for (int ks = 0; ks < 4; ks++) {
            int kb = ks * 32;
            uint32_t Ah[4][4], Al[4][4], Bh[2][4], Bl[2][4];
            #pragma unroll
            for (int mf = 0; mf < 4; mf++) {
                int rw = wm + mf * 16 + rowoff_a;
                ldsm_x4(swz(tAhi, rw, kb + kboff_a), Ah[mf][0], Ah[mf][1], Ah[mf][2], Ah[mf][3]);
                ldsm_x4(swz(tAlo, rw, kb + kboff_a), Al[mf][0], Al[mf][1], Al[mf][2], Al[mf][3]);
            }
            #pragma unroll
            for (int g = 0; g < 2; g++) {
                int rwb = wn + g * 16 + rowoff_b;
                ldsm_x4(swz(tBhi, rwb, kb + kboff_b), Bh[g][0], Bh[g][1], Bh[g][2], Bh[g][3]);
                ldsm_x4(swz(tBlo, rwb, kb + kboff_b), Bl[g][0], Bl[g][1], Bl[g][2], Bl[g][3]);
            }
            // pass 1: hi*hi
            #pragma unroll
            for (int mf = 0; mf < 4; mf++)
                #pragma unroll
                for (int nf = 0; nf < 4; nf++)
                    mma16816(acc[mf][nf], Ah[mf][0], Ah[mf][1], Ah[mf][2], Ah[mf][3],
                             Bh[nf >> 1][(nf & 1) * 2], Bh[nf >> 1][(nf & 1) * 2 + 1]);
            // pass 2: hi*lo
            #pragma unroll
            for (int mf = 0; mf < 4; mf++)
                #pragma unroll
                for (int nf = 0; nf < 4; nf++)
                    mma16816(acc[mf][nf], Ah[mf][0], Ah[mf][1], Ah[mf][2], Ah[mf][3],
                             Bl[nf >> 1][(nf & 1) * 2], Bl[nf >> 1][(nf & 1) * 2 + 1]);
            // pass 3: lo*hi
            #pragma unroll
            for (int mf = 0; mf < 4; mf++)
                #pragma unroll
                for (int nf = 0; nf < 4; nf++)
                    mma16816(acc[mf][nf], Al[mf][0], Al[mf][1], Al[mf][2], Al[mf][3],
                             Bh[nf >> 1][(nf & 1) * 2], Bh[nf >> 1][(nf & 1) * 2 + 1]);
        }
        __syncthreads();
    }

    // epilogue: accum regs -> C with bias
    #pragma unroll
    for (int mf = 0; mf < 4; mf++) {
        int row = r0 + wm + mf * 16 + (lane >> 2);
        #pragma unroll
        for (int nf = 0; nf < 4; nf++) {
            int col = c0 + wn + nf * 8 + 2 * (lane & 3);
            float2 v0, v1;
            v0.x = acc[mf][nf][0] + bias[col];
            v0.y = acc[mf][nf][1] + bias[col + 1];
            v1.x = acc[mf][nf][2] + bias[col];
            v1.y = acc[mf][nf][3] + bias[col + 1];
            *(float2*)(C + (size_t)row * Hn + col)       = v0;
            *(float2*)(C + (size_t)(row + 8) * Hn + col) = v1;
        }
    }
}

__global__ void __launch_bounds__(256, 1) qkv_tc(
    const float* __restrict__ bq, const float* __restrict__ bk, const float* __restrict__ bv)
{
    int z = blockIdx.z;
    const float* bias = (z == 0) ? bq : (z == 1) ? bk : bv;
    float* C = (z == 0) ? g_q : (z == 1) ? g_k : g_v;
    gemm_mma_body(g_xhi, g_xlo,
                  g_wthi + (size_t)z * W_ELEMS, g_wtlo + (size_t)z * W_ELEMS,
                  bias, C);
}

__global__ void __launch_bounds__(256, 1) out_tc(const float* __restrict__ bo, float* __restrict__ C)
{
    gemm_mma_body(g_ohi, g_olo,
                  g_wthi + (size_t)3 * W_ELEMS, g_wtlo + (size_t)3 * W_ELEMS,
                  bo, C);
}

// ---------------- flash attention 64x64 tiles (SIMT, unchanged) ----------------
#define QP 65
#define VP 68
#define SM_Q 0
#define SM_K (64 * QP)
#define SM_V (2 * 64 * QP)
#define SM_P (2 * 64 * QP + 64 * VP)
#define SM_TOTALF (2 * 64 * QP + 2 * 64 * VP)
#define SM_BYTES (SM_TOTALF * 4)

__global__ void __launch_bounds__(256) attn_kernel() {
    extern __shared__ float smf[];
    float* Qs = smf + SM_Q;
    float* Ks = smf + SM_K;
    float* Vs = smf + SM_V;
    float* Ps = smf + SM_P;

    int tid = threadIdx.x;
    int tx = tid & 15, ty = tid >> 4;
    int b = blockIdx.z, h = blockIdx.y;
    int i0 = blockIdx.x * 64;

    const float* qb  = g_q + (size_t)(b * Sn + i0) * Hn + h * HDn;
    const float* kb0 = g_k + (size_t)b * Sn * Hn + h * HDn;
    const float* vb0 = g_v + (size_t)b * Sn * Hn + h * HDn;
    const float* cbp = g_colb + b * Sn;

    #pragma unroll
    for (int r = 0; r < 4; r++) {
        int idx = tid + 256 * r;
        int row = idx >> 4, c4 = idx & 15;
        float4 v4 = *(const float4*)(qb + (size_t)row * Hn + c4 * 4);
        Qs[row*QP + c4*4+0] = v4.x; Qs[row*QP + c4*4+1] = v4.y;
        Qs[row*QP + c4*4+2] = v4.z; Qs[row*QP + c4*4+3] = v4.w;
    }

    int vti[4];
    #pragma unroll
    for (int i = 0; i < 4; i++) vti[i] = g_vt[b * Sn + i0 + ty * 4 + i];

    float m[4], l[4], acc[4][4];
    #pragma unroll
    for (int i = 0; i < 4; i++) {
        m[i] = -3.0e38f; l[i] = 0.f;
        #pragma unroll
        for (int j = 0; j < 4; j++) acc[i][j] = 0.f;
    }

    for (int jt = 0; jt < Sn / 64; jt++) {
        int j0 = jt * 64;
        __syncthreads();
        #pragma unroll
        for (int r = 0; r < 4; r++) {
            int idx = tid + 256 * r;
            int row = idx >> 4, c4 = idx & 15;
            float4 kv4 = *(const float4*)(kb0 + (size_t)(j0 + row) * Hn + c4 * 4);
            Ks[row*QP + c4*4+0] = kv4.x; Ks[row*QP + c4*4+1] = kv4.y;
            Ks[row*QP + c4*4+2] = kv4.z; Ks[row*QP + c4*4+3] = kv4.w;
            float4 vv4 = *(const float4*)(vb0 + (size_t)(j0 + row) * Hn + c4 * 4);
            *(float4*)&Vs[row * VP + c4 * 4] = vv4;
        }
        __syncthreads();

        float s[4][4];
        #pragma unroll
        for (int i = 0; i < 4; i++)
            #pragma unroll
            for (int j = 0; j < 4; j++) s[i][j] = 0.f;
        #pragma unroll 8
        for (int d = 0; d < 64; d++) {
            float qv[4], kv[4];
            #pragma unroll
            for (int i = 0; i < 4; i++) qv[i] = Qs[(ty*4+i)*QP + d];
            #pragma unroll
            for (int j = 0; j < 4; j++) kv[j] = Ks[(tx*4+j)*QP + d];
            #pragma unroll
            for (int i = 0; i < 4; i++)
                #pragma unroll
                for (int j = 0; j < 4; j++)
                    s[i][j] += qv[i] * kv[j];
        }

        float cbj[4];
        #pragma unroll
        for (int j = 0; j < 4; j++) cbj[j] = cbp[j0 + tx * 4 + j];
        #pragma unroll
        for (int i = 0; i < 4; i++)
            #pragma unroll
            for (int j = 0; j < 4; j++) {
                float val = s[i][j] * SCALEF + cbj[j];
                if (j0 + tx * 4 + j == vti[i]) val += VERB_BIAS;
                s[i][j] = val;
            }

        #pragma unroll
        for (int i = 0; i < 4; i++) {
            float rm = fmaxf(fmaxf(s[i][0], s[i][1]), fmaxf(s[i][2], s[i][3]));
            #pragma unroll
            for (int off = 8; off >= 1; off >>= 1)
                rm = fmaxf(rm, __shfl_xor_sync(0xffffffffu, rm, off, 16));
            float mn = fmaxf(m[i], rm);
            float corr = __expf(m[i] - mn);
            m[i] = mn;
            float p0 = __expf(s[i][0] - mn);
            float p1 = __expf(s[i][1] - mn);
            float p2 = __expf(s[i][2] - mn);
            float p3 = __expf(s[i][3] - mn);
            float sum = (p0 + p1) + (p2 + p3);
            #pragma unroll
            for (int off = 8; off >= 1; off >>= 1)
                sum += __shfl_xor_sync(0xffffffffu, sum, off, 16);
            l[i] = l[i] * corr + sum;
            #pragma unroll
            for (int j = 0; j < 4; j++) acc[i][j] *= corr;
            float4 pw = make_float4(p0, p1, p2, p3);
            *(float4*)&Ps[(ty * 4 + i) * VP + tx * 4] = pw;
        }
        __syncwarp();

        #pragma unroll 4
        for (int jj = 0; jj < 64; jj++) {
            float pv[4];
            #pragma unroll
            for (int i = 0; i < 4; i++) pv[i] = Ps[(ty * 4 + i) * VP + jj];
            float4 vv = *(const float4*)&Vs[jj * VP + tx * 4];
            #pragma unroll
            for (int i = 0; i < 4; i++) {
                acc[i][0] += pv[i] * vv.x;
                acc[i][1] += pv[i] * vv.y;
                acc[i][2] += pv[i] * vv.z;
                acc[i][3] += pv[i] * vv.w;
            }
        }
    }

    float* ob = g_o + (size_t)(b * Sn + i0) * Hn + h * HDn;
    #pragma unroll
    for (int i = 0; i < 4; i++) {
        float inv = 1.f / l[i];
        float4 v4;
        v4.x = acc[i][0] * inv; v4.y = acc[i][1] * inv;
        v4.z = acc[i][2] * inv; v4.w = acc[i][3] * inv;
        *(float4*)(ob + (size_t)(ty * 4 + i) * Hn + tx * 4) = v4;
    }
}

// ---------------- launch ----------------
extern "C" void kernel_launch(void* const* d_in, const int* in_sizes, int n_in,
                              void* d_out, int out_size) {
    const float* hidden = (const float*)d_in[0];
    const int*   morpho = (const int*)d_in[1];
    const float* Wq = (const float*)d_in[2];
    const float* bq = (const float*)d_in[3];
    const float* Wk = (const float*)d_in[4];
    const float* bk = (const float*)d_in[5];
    const float* Wv = (const float*)d_in[6];
    const float* bv = (const float*)d_in[7];
    const float* Wo = (const float*)d_in[8];
    const float* bo = (const float*)d_in[9];
    float* out = (float*)d_out;

    cudaFuncSetAttribute(attn_kernel,
                         cudaFuncAttributeMaxDynamicSharedMemorySize, SM_BYTES);
    cudaFuncSetAttribute(qkv_tc,
                         cudaFuncAttributeMaxDynamicSharedMemorySize, GT_SMEM_BYTES);
    cudaFuncSetAttribute(out_tc,
                         cudaFuncAttributeMaxDynamicSharedMemorySize, GT_SMEM_BYTES);

    static __nv_bfloat16 *xhi_p = nullptr, *xlo_p = nullptr, *ohi_p = nullptr, *olo_p = nullptr;
    static float *o_p = nullptr;
    if (!xhi_p) {
        cudaGetSymbolAddress((void**)&xhi_p, g_xhi);
        cudaGetSymbolAddress((void**)&xlo_p, g_xlo);
        cudaGetSymbolAddress((void**)&ohi_p, g_ohi);
        cudaGetSymbolAddress((void**)&olo_p, g_olo);
        cudaGetSymbolAddress((void**)&o_p,   g_o);
    }

    morpho_kernel<<<Bn, Sn>>>(morpho);
    convert_split<<<(Mtot*Hn/4 + 255) / 256, 256>>>(hidden, xhi_p, xlo_p, Mtot*Hn);
    transpose_convert_w<<<dim3(32, 32, 4), dim3(32, 8)>>>(Wq, Wk, Wv, Wo);
    qkv_tc<<<dim3(Hn/128, Mtot/128, 3), 256, GT_SMEM_BYTES>>>(bq, bk, bv);
    attn_kernel<<<dim3(Sn / 64, NHn, Bn), 256, SM_BYTES>>>();
    convert_split<<<(Mtot*Hn/4 + 255) / 256, 256>>>(o_p, ohi_p, olo_p, Mtot*Hn);
    out_tc<<<dim3(Hn/128, Mtot/128, 1), 256, GT_SMEM_BYTES>>>(bo, out);
}

// round 7
// speedup vs baseline: 2.8918x; 1.8504x over previous
#include <cuda_runtime.h>
#include <cuda_bf16.h>
#include <cstdint>

#define Bn 4
#define Sn 1024
#define Hn 1024
#define NHn 16
#define HDn 64
#define SCALEF 0.125f
#define VERB_BIAS 2.0f

#define Mtot (Bn*Sn)     // 4096
#define W_ELEMS (Hn*Hn)  // 1048576

// ---------------- scratch (allocation-free) ----------------
__device__ float g_colb[Bn*Sn];
__device__ int   g_vt[Bn*Sn];

__device__ __nv_bfloat16 g_xhi[Mtot*Hn];
__device__ __nv_bfloat16 g_xlo[Mtot*Hn];
__device__ __nv_bfloat16 g_qhi[Mtot*Hn];
__device__ __nv_bfloat16 g_qlo[Mtot*Hn];
__device__ __nv_bfloat16 g_khi[Mtot*Hn];
__device__ __nv_bfloat16 g_klo[Mtot*Hn];
__device__ __nv_bfloat16 g_vhi[Mtot*Hn];
__device__ __nv_bfloat16 g_vlo[Mtot*Hn];
__device__ __nv_bfloat16 g_ohi[Mtot*Hn];
__device__ __nv_bfloat16 g_olo[Mtot*Hn];
__device__ __nv_bfloat16 g_wthi[4*W_ELEMS];   // W^T per matrix: [n][k]
__device__ __nv_bfloat16 g_wtlo[4*W_ELEMS];

// ---------------- PTX helpers (family-portable only) ----------------
__device__ __forceinline__ uint32_t smem_to_u32(const void* p) {
    uint32_t a;
    asm("{ .reg .u64 t; cvta.to.shared.u64 t, %1; cvt.u32.u64 %0, t; }" : "=r"(a) : "l"(p));
    return a;
}
__device__ __forceinline__ void ldsm_x4(uint32_t addr, uint32_t& r0, uint32_t& r1,
                                        uint32_t& r2, uint32_t& r3) {
    asm volatile("ldmatrix.sync.aligned.m8n8.x4.shared.b16 {%0,%1,%2,%3}, [%4];"
        : "=r"(r0), "=r"(r1), "=r"(r2), "=r"(r3) : "r"(addr));
}
__device__ __forceinline__ void ldsm_x4_t(uint32_t addr, uint32_t& r0, uint32_t& r1,
                                          uint32_t& r2, uint32_t& r3) {
    asm volatile("ldmatrix.sync.aligned.m8n8.x4.trans.shared.b16 {%0,%1,%2,%3}, [%4];"
        : "=r"(r0), "=r"(r1), "=r"(r2), "=r"(r3) : "r"(addr));
}
__device__ __forceinline__ void mma16816(float* c, uint32_t a0, uint32_t a1,
                                         uint32_t a2, uint32_t a3,
                                         uint32_t b0, uint32_t b1) {
    asm volatile(
        "mma.sync.aligned.m16n8k16.row.col.f32.bf16.bf16.f32 "
        "{%0,%1,%2,%3}, {%4,%5,%6,%7}, {%8,%9}, {%0,%1,%2,%3};"
        : "+f"(c[0]), "+f"(c[1]), "+f"(c[2]), "+f"(c[3])
        : "r"(a0), "r"(a1), "r"(a2), "r"(a3), "r"(b0), "r"(b1));
}
__device__ __forceinline__ void cp_async16(uint32_t saddr, const void* gptr) {
    asm volatile("cp.async.cg.shared.global [%0], [%1], 16;" :: "r"(saddr), "l"(gptr));
}
#define CP_COMMIT() asm volatile("cp.async.commit_group;")
#define CP_WAIT0()  asm volatile("cp.async.wait_group 0;")
#define CP_WAIT1()  asm volatile("cp.async.wait_group 1;")

// SW128 swizzled address within a tile of 128B rows
__device__ __forceinline__ uint32_t swz(uint32_t base, int row, int kb) {
    uint32_t bo = (uint32_t)(row * 128 + kb);
    return base + (bo ^ ((bo >> 3) & 0x70));
}
__device__ __forceinline__ uint32_t swzoff(int row, int kb) {
    uint32_t bo = (uint32_t)(row * 128 + kb);
    return bo ^ ((bo >> 3) & 0x70);
}
__device__ __forceinline__ uint32_t pack_bf16(float a, float b) {
    __nv_bfloat162 h = __float22bfloat162_rn(make_float2(a, b));
    return *(uint32_t*)&h;
}

// ---------------- morpho preprocessing ----------------
__global__ void morpho_kernel(const int* __restrict__ morpho) {
    int b = blockIdx.x;
    int i = threadIdx.x;
    const int* mrow = morpho + b * Sn;
    __shared__ unsigned char isv[Sn];
    __shared__ int anyv;
    if (i == 0) anyv = 0;
    __syncthreads();
    int t = mrow[i];
    unsigned char iv = (t == 2);
    isv[i] = iv;
    if (iv) anyv = 1;
    g_colb[b*Sn + i] = (1.5f*0.5f) * (t == 0) + (1.2f*0.3f) * (t == 1);
    __syncthreads();
    int nearest = -1;
    if (anyv) {
        for (int d = 0; d < Sn; d++) {
            int jl = i - d;
            if (jl >= 0 && isv[jl]) { nearest = jl; break; }
            int jr = i + d;
            if (jr < Sn && isv[jr]) { nearest = jr; break; }
        }
    }
    g_vt[b*Sn + i] = nearest;
}

// ---------------- conversion kernels ----------------
__global__ void convert_split(const float* __restrict__ src,
                              __nv_bfloat16* __restrict__ hi,
                              __nv_bfloat16* __restrict__ lo, int n) {
    int idx = (blockIdx.x * blockDim.x + threadIdx.x) * 4;
    if (idx < n) {
        float4 x = *(const float4*)(src + idx);
        __nv_bfloat16 h0 = __float2bfloat16_rn(x.x);
        __nv_bfloat16 h1 = __float2bfloat16_rn(x.y);
        __nv_bfloat16 h2 = __float2bfloat16_rn(x.z);
        __nv_bfloat16 h3 = __float2bfloat16_rn(x.w);
        __nv_bfloat162 hp0, hp1, lp0, lp1;
        hp0.x = h0; hp0.y = h1; hp1.x = h2; hp1.y = h3;
        lp0.x = __float2bfloat16_rn(x.x - __bfloat162float(h0));
        lp0.y = __float2bfloat16_rn(x.y - __bfloat162float(h1));
        lp1.x = __float2bfloat16_rn(x.z - __bfloat162float(h2));
        lp1.y = __float2bfloat16_rn(x.w - __bfloat162float(h3));
        *(__nv_bfloat162*)(hi + idx) = hp0;
        *(__nv_bfloat162*)(hi + idx + 2) = hp1;
        *(__nv_bfloat162*)(lo + idx) = lp0;
        *(__nv_bfloat162*)(lo + idx + 2) = lp1;
    }
}

__global__ void transpose_convert_w(const float* __restrict__ Wq, const float* __restrict__ Wk,
                                    const float* __restrict__ Wv, const float* __restrict__ Wo) {
    __shared__ float t[32][33];
    int z = blockIdx.z;
    const float* W = (z == 0) ? Wq : (z == 1) ? Wk : (z == 2) ? Wv : Wo;
    __nv_bfloat16* whi = g_wthi + (size_t)z * W_ELEMS;
    __nv_bfloat16* wlo = g_wtlo + (size_t)z * W_ELEMS;
    int n0 = blockIdx.x * 32, k0 = blockIdx.y * 32;
    int tx = threadIdx.x, ty = threadIdx.y;
    #pragma unroll
    for (int i = 0; i < 4; i++) {
        int kr = ty + i * 8;
        t[kr][tx] = W[(size_t)(k0 + kr) * Hn + n0 + tx];
    }
    __syncthreads();
    #pragma unroll
    for (int i = 0; i < 4; i++) {
        int nr = ty + i * 8;
        float x = t[tx][nr];
        __nv_bfloat16 h = __float2bfloat16_rn(x);
        whi[(size_t)(n0 + nr) * Hn + k0 + tx] = h;
        wlo[(size_t)(n0 + nr) * Hn + k0 + tx] = __float2bfloat16_rn(x - __bfloat162float(h));
    }
}

// ---------------- mma.sync GEMM with cp.async double buffering ----------------
// 128x128 CTA tile, K-chunks of 64; buffers: 4 tiles x 16KB x 2 = 128KB smem.
#define GT_TILE 16384
#define GT_BUF  (4*GT_TILE)          // 65536
#define GT_SMEM_BYTES (2*GT_BUF)     // 131072
#define NCHUNK 16

template<int BF16OUT>
__device__ __forceinline__ void gemm_mma_body(
    const __nv_bfloat16* __restrict__ Ahi, const __nv_bfloat16* __restrict__ Alo,
    const __nv_bfloat16* __restrict__ Bhi, const __nv_bfloat16* __restrict__ Blo,
    const float* __restrict__ bias, float* __restrict__ C,
    __nv_bfloat16* __restrict__ Chi, __nv_bfloat16* __restrict__ Clo)
{
    extern __shared__ char smc[];
    uint32_t smb = smem_to_u32(smc);

    int tid = threadIdx.x;
    int wid = tid >> 5, lane = tid & 31;
    int r0 = blockIdx.y * 128;
    int c0 = blockIdx.x * 128;
    int wm = (wid >> 2) * 64;
    int wn = (wid & 3) * 32;

    int la = lane & 7, qa = lane >> 3;
    int rowoff_a = (qa & 1) * 8 + la;
    int kboff_a  = (qa >> 1) * 16;
    int rowoff_b = (qa >> 1) * 8 + la;
    int kboff_b  = (qa & 1) * 16;

    float acc[4][4][4];
    #pragma unroll
    for (int mf = 0; mf < 4; mf++)
        #pragma unroll
        for (int nf = 0; nf < 4; nf++)
            #pragma unroll
            for (int j = 0; j < 4; j++) acc[mf][nf][j] = 0.f;

    // prefetch chunk 0
    {
        uint32_t base = smb;
        #pragma unroll
        for (int r = 0; r < 4; r++) {
            int idx = tid + 256 * r;
            int row = idx >> 3, c16 = idx & 7;
            uint32_t sw = swzoff(row, c16 * 16);
            size_t ga = (size_t)(r0 + row) * Hn + c16 * 8;
            size_t gb = (size_t)(c0 + row) * Hn + c16 * 8;
            cp_async16(base + sw,             Ahi + ga);
            cp_async16(base + GT_TILE + sw,   Alo + ga);
            cp_async16(base + 2*GT_TILE + sw, Bhi + gb);
            cp_async16(base + 3*GT_TILE + sw, Blo + gb);
        }
        CP_COMMIT();
    }

    for (int ch = 0; ch < NCHUNK; ch++) {
        if (ch + 1 < NCHUNK) {
            uint32_t base = smb + ((ch + 1) & 1) * GT_BUF;
            int k0 = (ch + 1) * 64;
            #pragma unroll
            for (int r = 0; r < 4; r++) {
                int idx = tid + 256 * r;
                int row = idx >> 3, c16 = idx & 7;
                uint32_t sw = swzoff(row, c16 * 16);
                size_t ga = (size_t)(r0 + row) * Hn + k0 + c16 * 8;
                size_t gb = (size_t)(c0 + row) * Hn + k0 + c16 * 8;
                cp_async16(base + sw,             Ahi + ga);
                cp_async16(base + GT_TILE + sw,   Alo + ga);
                cp_async16(base + 2*GT_TILE + sw, Bhi + gb);
                cp_async16(base + 3*GT_TILE + sw, Blo + gb);
            }
            CP_COMMIT();
            CP_WAIT1();
        } else {
            CP_WAIT0();
        }
        __syncthreads();

        uint32_t cb = smb + (ch & 1) * GT_BUF;
        uint32_t tAhi = cb, tAlo = cb + GT_TILE, tBhi = cb + 2*GT_TILE, tBlo = cb + 3*GT_TILE;

        #pragma unroll
        for (int ks = 0; ks < 4; ks++) {
            int kb = ks * 32;
            uint32_t Ah[4][4], Al[4][4], Bh[2][4], Bl[2][4];
            #pragma unroll
            for (int mf = 0; mf < 4; mf++) {
                int rw = wm + mf * 16 + rowoff_a;
                ldsm_x4(swz(tAhi, rw, kb + kboff_a), Ah[mf][0], Ah[mf][1], Ah[mf][2], Ah[mf][3]);
                ldsm_x4(swz(tAlo, rw, kb + kboff_a), Al[mf][0], Al[mf][1], Al[mf][2], Al[mf][3]);
            }
            #pragma unroll
            for (int g = 0; g < 2; g++) {
                int rwb = wn + g * 16 + rowoff_b;
                ldsm_x4(swz(tBhi, rwb, kb + kboff_b), Bh[g][0], Bh[g][1], Bh[g][2], Bh[g][3]);
                ldsm_x4(swz(tBlo, rwb, kb + kboff_b), Bl[g][0], Bl[g][1], Bl[g][2], Bl[g][3]);
            }
            #pragma unroll
            for (int mf = 0; mf < 4; mf++)
                #pragma unroll
                for (int nf = 0; nf < 4; nf++)
                    mma16816(acc[mf][nf], Ah[mf][0], Ah[mf][1], Ah[mf][2], Ah[mf][3],
                             Bh[nf >> 1][(nf & 1) * 2], Bh[nf >> 1][(nf & 1) * 2 + 1]);
            #pragma unroll
            for (int mf = 0; mf < 4; mf++)
                #pragma unroll
                for (int nf = 0; nf < 4; nf++)
                    mma16816(acc[mf][nf], Ah[mf][0], Ah[mf][1], Ah[mf][2], Ah[mf][3],
                             Bl[nf >> 1][(nf & 1) * 2], Bl[nf >> 1][(nf & 1) * 2 + 1]);
            #pragma unroll
            for (int mf = 0; mf < 4; mf++)
                #pragma unroll
                for (int nf = 0; nf < 4; nf++)
                    mma16816(acc[mf][nf], Al[mf][0], Al[mf][1], Al[mf][2], Al[mf][3],
                             Bh[nf >> 1][(nf & 1) * 2], Bh[nf >> 1][(nf & 1) * 2 + 1]);
        }
        __syncthreads();
    }

    #pragma unroll
    for (int mf = 0; mf < 4; mf++) {
        int row = r0 + wm + mf * 16 + (lane >> 2);
        #pragma unroll
        for (int nf = 0; nf < 4; nf++) {
            int col = c0 + wn + nf * 8 + 2 * (lane & 3);
            float b0 = bias[col], b1 = bias[col + 1];
            float v0 = acc[mf][nf][0] + b0, v1 = acc[mf][nf][1] + b1;
            float v2 = acc[mf][nf][2] + b0, v3 = acc[mf][nf][3] + b1;
            if (BF16OUT) {
                __nv_bfloat162 h0 = __float22bfloat162_rn(make_float2(v0, v1));
                __nv_bfloat162 l0 = __float22bfloat162_rn(make_float2(
                    v0 - __bfloat162float(h0.x), v1 - __bfloat162float(h0.y)));
                __nv_bfloat162 h1 = __float22bfloat162_rn(make_float2(v2, v3));
                __nv_bfloat162 l1 = __float22bfloat162_rn(make_float2(
                    v2 - __bfloat162float(h1.x), v3 - __bfloat162float(h1.y)));
                *(__nv_bfloat162*)(Chi + (size_t)row * Hn + col)       = h0;
                *(__nv_bfloat162*)(Clo + (size_t)row * Hn + col)       = l0;
                *(__nv_bfloat162*)(Chi + (size_t)(row + 8) * Hn + col) = h1;
                *(__nv_bfloat162*)(Clo + (size_t)(row + 8) * Hn + col) = l1;
            } else {
                *(float2*)(C + (size_t)row * Hn + col)       = make_float2(v0, v1);
                *(float2*)(C + (size_t)(row + 8) * Hn + col) = make_float2(v2, v3);
            }
        }
    }
}

__global__ void __launch_bounds__(256, 1) qkv_tc(
    const float* __restrict__ bq, const float* __restrict__ bk, const float* __restrict__ bv)
{
    int z = blockIdx.z;
    const float* bias = (z == 0) ? bq : (z == 1) ? bk : bv;
    __nv_bfloat16* Chi = (z == 0) ? g_qhi : (z == 1) ? g_khi : g_vhi;
    __nv_bfloat16* Clo = (z == 0) ? g_qlo : (z == 1) ? g_klo : g_vlo;
    gemm_mma_body<1>(g_xhi, g_xlo,
                     g_wthi + (size_t)z * W_ELEMS, g_wtlo + (size_t)z * W_ELEMS,
                     bias, nullptr, Chi, Clo);
}

__global__ void __launch_bounds__(256, 1) out_tc(const float* __restrict__ bo, float* __restrict__ C)
{
    gemm_mma_body<0>(g_ohi, g_olo,
                     g_wthi + (size_t)3 * W_ELEMS, g_wtlo + (size_t)3 * W_ELEMS,
                     bo, C, nullptr, nullptr);
}

// ---------------- flash attention on mma.sync ----------------
// CTA: 128 q-rows x (b,h). 8 warps, each 16 q-rows. j tiles of 64, double-buffered cp.async.
// smem: [0,4KB) colb; [4KB, 4KB+64KB) two KV buffers (Khi,Klo,Vhi,Vlo @ 8KB each).
// Q staged once into buffer region, extracted to registers before KV loads start.
#define AT_KVBUF 32768
#define AT_SMEM (4096 + 2*AT_KVBUF)  // 69632

__global__ void __launch_bounds__(256) attn_mma() {
    extern __shared__ char smc[];
    uint32_t smb = smem_to_u32(smc);
    float* colb_sm = (float*)smc;
    uint32_t bufb = smb + 4096;

    int tid = threadIdx.x;
    int wid = tid >> 5, lane = tid & 31;
    int b = blockIdx.z, h = blockIdx.y;
    int i0 = blockIdx.x * 128;

    int la = lane & 7, qa = lane >> 3;
    int roa = (qa & 1) * 8 + la, kba = (qa >> 1) * 16;   // A-style / trans-V style
    int rob = (qa >> 1) * 8 + la, kbb = (qa & 1) * 16;   // B-style (K)

    // stage colb
    #pragma unroll
    for (int r = 0; r < 4; r++) colb_sm[tid + 256 * r] = g_colb[b * Sn + tid + 256 * r];

    // stage Q tile [128 x 64] hi/lo into buffer region, then extract to regs
    {
        const __nv_bfloat16* qhb = g_qhi + (size_t)(b * Sn + i0) * Hn + h * HDn;
        const __nv_bfloat16* qlb = g_qlo + (size_t)(b * Sn + i0) * Hn + h * HDn;
        #pragma unroll
        for (int r = 0; r < 4; r++) {
            int idx = tid + 256 * r;
            int row = idx >> 3, c16 = idx & 7;
            uint32_t sw = swzoff(row, c16 * 16);
            size_t ga = (size_t)row * Hn + c16 * 8;
            *(uint4*)(smc + 4096 + sw)         = *(const uint4*)(qhb + ga);
            *(uint4*)(smc + 4096 + 16384 + sw) = *(const uint4*)(qlb + ga);
        }
    }
    __syncthreads();
    uint32_t Qh[4][4], Ql[4][4];
    #pragma unroll
    for (int kd = 0; kd < 4; kd++) {
        int rw = wid * 16 + roa;
        ldsm_x4(swz(bufb, rw, kd * 32 + kba),         Qh[kd][0], Qh[kd][1], Qh[kd][2], Qh[kd][3]);
        ldsm_x4(swz(bufb + 16384, rw, kd * 32 + kba), Ql[kd][0], Ql[kd][1], Ql[kd][2], Ql[kd][3]);
    }
    __syncthreads();   // all ldmatrix done before cp.async overwrites region

    int r_g = i0 + wid * 16 + (lane >> 2);
    int vt0 = g_vt[b * Sn + r_g];
    int vt1 = g_vt[b * Sn + r_g + 8];

    float m0 = -3.0e38f, m1 = -3.0e38f, l0 = 0.f, l1 = 0.f;
    float acc[8][4];
    #pragma unroll
    for (int t = 0; t < 8; t++)
        #pragma unroll
        for (int j = 0; j < 4; j++) acc[t][j] = 0.f;

    const __nv_bfloat16* khb = g_khi + (size_t)b * Sn * Hn + h * HDn;
    const __nv_bfloat16* klb = g_klo + (size_t)b * Sn * Hn + h * HDn;
    const __nv_bfloat16* vhb = g_vhi + (size_t)b * Sn * Hn + h * HDn;
    const __nv_bfloat16* vlb = g_vlo + (size_t)b * Sn * Hn + h * HDn;

    // prefetch jtile 0
    {
        uint32_t base = bufb;
        #pragma unroll
        for (int r = 0; r < 2; r++) {
            int idx = tid + 256 * r;
            int row = idx >> 3, c16 = idx & 7;
            uint32_t sw = swzoff(row, c16 * 16);
            size_t go = (size_t)row * Hn + c16 * 8;
            cp_async16(base + sw,         khb + go);
            cp_async16(base + 8192 + sw,  klb + go);
            cp_async16(base + 16384 + sw, vhb + go);
            cp_async16(base + 24576 + sw, vlb + go);
        }
        CP_COMMIT();
    }

    for (int jt = 0; jt < Sn / 64; jt++) {
        if (jt + 1 < Sn / 64) {
            uint32_t base = bufb + ((jt + 1) & 1) * AT_KVBUF;
            int j0 = (jt + 1) * 64;
            #pragma unroll
            for (int r = 0; r < 2; r++) {
                int idx = tid + 256 * r;
                int row = idx >> 3, c16 = idx & 7;
                uint32_t sw = swzoff(row, c16 * 16);
                size_t go = (size_t)(j0 + row) * Hn + c16 * 8;
                cp_async16(base + sw,         khb + go);
                cp_async16(base + 8192 + sw,  klb + go);
                cp_async16(base + 16384 + sw, vhb + go);
                cp_async16(base + 24576 + sw, vlb + go);
            }
            CP_COMMIT();
            CP_WAIT1();
        } else {
            CP_WAIT0();
        }
        __syncthreads();

        uint32_t cb = bufb + (jt & 1) * AT_KVBUF;
        uint32_t Kh = cb, Kl = cb + 8192, Vh = cb + 16384, Vl = cb + 24576;

        // S = Q K^T (3-pass hi/lo), 16 x 64 per warp
        float s[8][4];
        #pragma unroll
        for (int t = 0; t < 8; t++)
            #pragma unroll
            for (int j = 0; j < 4; j++) s[t][j] = 0.f;
        #pragma unroll
        for (int kd = 0; kd < 4; kd++) {
            #pragma unroll
            for (int ng = 0; ng < 4; ng++) {
                uint32_t bh0, bh1, bh2, bh3, bl0, bl1, bl2, bl3;
                ldsm_x4(swz(Kh, ng * 16 + rob, kd * 32 + kbb), bh0, bh1, bh2, bh3);
                ldsm_x4(swz(Kl, ng * 16 + rob, kd * 32 + kbb), bl0, bl1, bl2, bl3);
                mma16816(s[2*ng],   Qh[kd][0], Qh[kd][1], Qh[kd][2], Qh[kd][3], bh0, bh1);
                mma16816(s[2*ng+1], Qh[kd][0], Qh[kd][1], Qh[kd][2], Qh[kd][3], bh2, bh3);
                mma16816(s[2*ng],   Qh[kd][0], Qh[kd][1], Qh[kd][2], Qh[kd][3], bl0, bl1);
                mma16816(s[2*ng+1], Qh[kd][0], Qh[kd][1], Qh[kd][2], Qh[kd][3], bl2, bl3);
                mma16816(s[2*ng],   Ql[kd][0], Ql[kd][1], Ql[kd][2], Ql[kd][3], bh0, bh1);
                mma16816(s[2*ng+1], Ql[kd][0], Ql[kd][1], Ql[kd][2], Ql[kd][3], bh2, bh3);
            }
        }

        // scale + bias + online softmax
        float rmax0 = -3.0e38f, rmax1 = -3.0e38f;
        #pragma unroll
        for (int t = 0; t < 8; t++) {
            int jc = jt * 64 + t * 8 + (lane & 3) * 2;
            float cb0 = colb_sm[jc], cb1 = colb_sm[jc + 1];
            s[t][0] = s[t][0] * SCALEF + cb0 + (jc     == vt0 ? VERB_BIAS : 0.f);
            s[t][1] = s[t][1] * SCALEF + cb1 + (jc + 1 == vt0 ? VERB_BIAS : 0.f);
            s[t][2] = s[t][2] * SCALEF + cb0 + (jc     == vt1 ? VERB_BIAS : 0.f);
            s[t][3] = s[t][3] * SCALEF + cb1 + (jc + 1 == vt1 ? VERB_BIAS : 0.f);
            rmax0 = fmaxf(rmax0, fmaxf(s[t][0], s[t][1]));
            rmax1 = fmaxf(rmax1, fmaxf(s[t][2], s[t][3]));
        }
        rmax0 = fmaxf(rmax0, __shfl_xor_sync(0xffffffffu, rmax0, 1));
        rmax0 = fmaxf(rmax0, __shfl_xor_sync(0xffffffffu, rmax0, 2));
        rmax1 = fmaxf(rmax1, __shfl_xor_sync(0xffffffffu, rmax1, 1));
        rmax1 = fmaxf(rmax1, __shfl_xor_sync(0xffffffffu, rmax1, 2));
        float mn0 = fmaxf(m0, rmax0), mn1 = fmaxf(m1, rmax1);
        float cr0 = __expf(m0 - mn0), cr1 = __expf(m1 - mn1);
        m0 = mn0; m1 = mn1;

        float sum0 = 0.f, sum1 = 0.f;
        uint32_t Ph[4][4], Pl[4][4];
        #pragma unroll
        for (int g = 0; g < 4; g++) {
            #pragma unroll
            for (int hh = 0; hh < 2; hh++) {
                int t = 2 * g + hh;
                float p0 = __expf(s[t][0] - mn0);
                float p1 = __expf(s[t][1] - mn0);
                float p2 = __expf(s[t][2] - mn1);
                float p3 = __expf(s[t][3] - mn1);
                sum0 += p0 + p1; sum1 += p2 + p3;
                uint32_t h01 = pack_bf16(p0, p1);
                uint32_t h23 = pack_bf16(p2, p3);
                __nv_bfloat162 hh01 = *(__nv_bfloat162*)&h01;
                __nv_bfloat162 hh23 = *(__nv_bfloat162*)&h23;
                uint32_t l01 = pack_bf16(p0 - __bfloat162float(hh01.x), p1 - __bfloat162float(hh01.y));
                uint32_t l23 = pack_bf16(p2 - __bfloat162float(hh23.x), p3 - __bfloat162float(hh23.y));
                Ph[g][hh * 2]     = h01;
                Ph[g][hh * 2 + 1] = h23;
                Pl[g][hh * 2]     = l01;
                Pl[g][hh * 2 + 1] = l23;
            }
        }
        sum0 += __shfl_xor_sync(0xffffffffu, sum0, 1);
        sum0 += __shfl_xor_sync(0xffffffffu, sum0, 2);
        sum1 += __shfl_xor_sync(0xffffffffu, sum1, 1);
        sum1 += __shfl_xor_sync(0xffffffffu, sum1, 2);
        l0 = l0 * cr0 + sum0;
        l1 = l1 * cr1 + sum1;
        #pragma unroll
        for (int t = 0; t < 8; t++) {
            acc[t][0] *= cr0; acc[t][1] *= cr0;
            acc[t][2] *= cr1; acc[t][3] *= cr1;
        }

        // O += P V (3-pass). V^T fragments via ldmatrix.trans on [j][d] tiles.
        #pragma unroll
        for (int g = 0; g < 4; g++) {
            #pragma unroll
            for (int gd = 0; gd < 4; gd++) {
                uint32_t vh0, vh1, vh2, vh3, vl0, vl1, vl2, vl3;
                ldsm_x4_t(swz(Vh, g * 16 + roa, gd * 32 + kba), vh0, vh1, vh2, vh3);
                ldsm_x4_t(swz(Vl, g * 16 + roa, gd * 32 + kba), vl0, vl1, vl2, vl3);
                mma16816(acc[2*gd],   Ph[g][0], Ph[g][1], Ph[g][2], Ph[g][3], vh0, vh1);
                mma16816(acc[2*gd+1], Ph[g][0], Ph[g][1], Ph[g][2], Ph[g][3], vh2, vh3);
                mma16816(acc[2*gd],   Ph[g][0], Ph[g][1], Ph[g][2], Ph[g][3], vl0, vl1);
                mma16816(acc[2*gd+1], Ph[g][0], Ph[g][1], Ph[g][2], Ph[g][3], vl2, vl3);
                mma16816(acc[2*gd],   Pl[g][0], Pl[g][1], Pl[g][2], Pl[g][3], vh0, vh1);
                mma16816(acc[2*gd+1], Pl[g][0], Pl[g][1], Pl[g][2], Pl[g][3], vh2, vh3);
            }
        }
        __syncthreads();
    }

    // epilogue: normalize, split hi/lo, store
    float inv0 = 1.f / l0, inv1 = 1.f / l1;
    __nv_bfloat16* ohb = g_ohi + (size_t)(b * Sn + r_g) * Hn + h * HDn;
    __nv_bfloat16* olb = g_olo + (size_t)(b * Sn + r_g) * Hn + h * HDn;
    #pragma unroll
    for (int t = 0; t < 8; t++) {
        int d = t * 8 + (lane & 3) * 2;
        float v0 = acc[t][0] * inv0, v1 = acc[t][1] * inv0;
        float v2 = acc[t][2] * inv1, v3 = acc[t][3] * inv1;
        __nv_bfloat162 h0 = __float22bfloat162_rn(make_float2(v0, v1));
        __nv_bfloat162 l0v = __float22bfloat162_rn(make_float2(
            v0 - __bfloat162float(h0.x), v1 - __bfloat162float(h0.y)));
        __nv_bfloat162 h1 = __float22bfloat162_rn(make_float2(v2, v3));
        __nv_bfloat162 l1v = __float22bfloat162_rn(make_float2(
            v2 - __bfloat162float(h1.x), v3 - __bfloat162float(h1.y)));
        *(__nv_bfloat162*)(ohb + d)                 = h0;
        *(__nv_bfloat162*)(olb + d)                 = l0v;
        *(__nv_bfloat162*)(ohb + (size_t)8 * Hn + d) = h1;
        *(__nv_bfloat162*)(olb + (size_t)8 * Hn + d) = l1v;
    }
}

// ---------------- launch ----------------
extern "C" void kernel_launch(void* const* d_in, const int* in_sizes, int n_in,
                              void* d_out, int out_size) {
    const float* hidden = (const float*)d_in[0];
    const int*   morpho = (const int*)d_in[1];
    const float* Wq = (const float*)d_in[2];
    const float* bq = (const float*)d_in[3];
    const float* Wk = (const float*)d_in[4];
    const float* bk = (const float*)d_in[5];
    const float* Wv = (const float*)d_in[6];
    const float* bv = (const float*)d_in[7];
    const float* Wo = (const float*)d_in[8];
    const float* bo = (const float*)d_in[9];
    float* out = (float*)d_out;

    cudaFuncSetAttribute(qkv_tc,
                         cudaFuncAttributeMaxDynamicSharedMemorySize, GT_SMEM_BYTES);
    cudaFuncSetAttribute(out_tc,
                         cudaFuncAttributeMaxDynamicSharedMemorySize, GT_SMEM_BYTES);
    cudaFuncSetAttribute(attn_mma,
                         cudaFuncAttributeMaxDynamicSharedMemorySize, AT_SMEM);

    static __nv_bfloat16 *xhi_p = nullptr, *xlo_p = nullptr;
    if (!xhi_p) {
        cudaGetSymbolAddress((void**)&xhi_p, g_xhi);
        cudaGetSymbolAddress((void**)&xlo_p, g_xlo);
    }

    morpho_kernel<<<Bn, Sn>>>(morpho);
    convert_split<<<(Mtot*Hn/4 + 255) / 256, 256>>>(hidden, xhi_p, xlo_p, Mtot*Hn);
    transpose_convert_w<<<dim3(32, 32, 4), dim3(32, 8)>>>(Wq, Wk, Wv, Wo);
    qkv_tc<<<dim3(Hn/128, Mtot/128, 3), 256, GT_SMEM_BYTES>>>(bq, bk, bv);
    attn_mma<<<dim3(Sn/128, NHn, Bn), 256, AT_SMEM>>>();
    out_tc<<<dim3(Hn/128, Mtot/128, 1), 256, GT_SMEM_BYTES>>>(bo, out);
}

// round 10
// speedup vs baseline: 2.9301x; 1.0133x over previous
#include <cuda_runtime.h>
#include <cuda_bf16.h>
#include <cstdint>

#define Bn 4
#define Sn 1024
#define Hn 1024
#define NHn 16
#define HDn 64
#define SCALEF 0.125f
#define LOG2E 1.4426950408889634f
#define SCALE_L2E (0.125f * 1.4426950408889634f)
#define VERB_L2E (2.0f * 1.4426950408889634f)

#define Mtot (Bn*Sn)     // 4096
#define W_ELEMS (Hn*Hn)  // 1048576

// ---------------- scratch (allocation-free) ----------------
__device__ float g_colb[Bn*Sn];
__device__ int   g_vt[Bn*Sn];

__device__ __nv_bfloat16 g_xhi[Mtot*Hn];
__device__ __nv_bfloat16 g_xlo[Mtot*Hn];
__device__ __nv_bfloat16 g_qhi[Mtot*Hn];
__device__ __nv_bfloat16 g_qlo[Mtot*Hn];
__device__ __nv_bfloat16 g_khi[Mtot*Hn];
__device__ __nv_bfloat16 g_klo[Mtot*Hn];
__device__ __nv_bfloat16 g_vhi[Mtot*Hn];
__device__ __nv_bfloat16 g_vlo[Mtot*Hn];
__device__ __nv_bfloat16 g_ohi[Mtot*Hn];
__device__ __nv_bfloat16 g_olo[Mtot*Hn];
__device__ __nv_bfloat16 g_wthi[4*W_ELEMS];   // W^T per matrix: [n][k]
__device__ __nv_bfloat16 g_wtlo[4*W_ELEMS];

// ---------------- PTX helpers (family-portable only) ----------------
__device__ __forceinline__ uint32_t smem_to_u32(const void* p) {
    uint32_t a;
    asm("{ .reg .u64 t; cvta.to.shared.u64 t, %1; cvt.u32.u64 %0, t; }" : "=r"(a) : "l"(p));
    return a;
}
__device__ __forceinline__ void ldsm_x4(uint32_t addr, uint32_t& r0, uint32_t& r1,
                                        uint32_t& r2, uint32_t& r3) {
    asm volatile("ldmatrix.sync.aligned.m8n8.x4.shared.b16 {%0,%1,%2,%3}, [%4];"
        : "=r"(r0), "=r"(r1), "=r"(r2), "=r"(r3) : "r"(addr));
}
__device__ __forceinline__ void ldsm_x4_t(uint32_t addr, uint32_t& r0, uint32_t& r1,
                                          uint32_t& r2, uint32_t& r3) {
    asm volatile("ldmatrix.sync.aligned.m8n8.x4.trans.shared.b16 {%0,%1,%2,%3}, [%4];"
        : "=r"(r0), "=r"(r1), "=r"(r2), "=r"(r3) : "r"(addr));
}
__device__ __forceinline__ void mma16816(float* c, uint32_t a0, uint32_t a1,
                                         uint32_t a2, uint32_t a3,
                                         uint32_t b0, uint32_t b1) {
    asm volatile(
        "mma.sync.aligned.m16n8k16.row.col.f32.bf16.bf16.f32 "
        "{%0,%1,%2,%3}, {%4,%5,%6,%7}, {%8,%9}, {%0,%1,%2,%3};"
        : "+f"(c[0]), "+f"(c[1]), "+f"(c[2]), "+f"(c[3])
        : "r"(a0), "r"(a1), "r"(a2), "r"(a3), "r"(b0), "r"(b1));
}
__device__ __forceinline__ void cp_async16(uint32_t saddr, const void* gptr) {
    asm volatile("cp.async.cg.shared.global [%0], [%1], 16;" :: "r"(saddr), "l"(gptr));
}
#define CP_COMMIT() asm volatile("cp.async.commit_group;")
#define CP_WAIT0()  asm volatile("cp.async.wait_group 0;")
#define CP_WAIT1()  asm volatile("cp.async.wait_group 1;")
#define CP_WAIT2()  asm volatile("cp.async.wait_group 2;")

__device__ __forceinline__ float ex2f(float x) {
    float y;
    asm("ex2.approx.ftz.f32 %0, %1;" : "=f"(y) : "f"(x));
    return y;
}

// SW128 swizzled address within a tile of 128B rows
__device__ __forceinline__ uint32_t swz(uint32_t base, int row, int kb) {
    uint32_t bo = (uint32_t)(row * 128 + kb);
    return base + (bo ^ ((bo >> 3) & 0x70));
}
__device__ __forceinline__ uint32_t swzoff(int row, int kb) {
    uint32_t bo = (uint32_t)(row * 128 + kb);
    return bo ^ ((bo >> 3) & 0x70);
}
__device__ __forceinline__ uint32_t pack_bf16(float a, float b) {
    __nv_bfloat162 h = __float22bfloat162_rn(make_float2(a, b));
    return *(uint32_t*)&h;
}

// ---------------- morpho preprocessing ----------------
__global__ void morpho_kernel(const int* __restrict__ morpho) {
    int b = blockIdx.x;
    int i = threadIdx.x;
    const int* mrow = morpho + b * Sn;
    __shared__ unsigned char isv[Sn];
    __shared__ int anyv;
    if (i == 0) anyv = 0;
    __syncthreads();
    int t = mrow[i];
    unsigned char iv = (t == 2);
    isv[i] = iv;
    if (iv) anyv = 1;
    g_colb[b*Sn + i] = (1.5f*0.5f) * (t == 0) + (1.2f*0.3f) * (t == 1);
    __syncthreads();
    int nearest = -1;
    if (anyv) {
        for (int d = 0; d < Sn; d++) {
            int jl = i - d;
            if (jl >= 0 && isv[jl]) { nearest = jl; break; }
            int jr = i + d;
            if (jr < Sn && isv[jr]) { nearest = jr; break; }
        }
    }
    g_vt[b*Sn + i] = nearest;
}

// ---------------- conversion kernels ----------------
__global__ void convert_split(const float* __restrict__ src,
                              __nv_bfloat16* __restrict__ hi,
                              __nv_bfloat16* __restrict__ lo, int n) {
    int idx = (blockIdx.x * blockDim.x + threadIdx.x) * 4;
    if (idx < n) {
        float4 x = *(const float4*)(src + idx);
        __nv_bfloat16 h0 = __float2bfloat16_rn(x.x);
        __nv_bfloat16 h1 = __float2bfloat16_rn(x.y);
        __nv_bfloat16 h2 = __float2bfloat16_rn(x.z);
        __nv_bfloat16 h3 = __float2bfloat16_rn(x.w);
        __nv_bfloat162 hp0, hp1, lp0, lp1;
        hp0.x = h0; hp0.y = h1; hp1.x = h2; hp1.y = h3;
        lp0.x = __float2bfloat16_rn(x.x - __bfloat162float(h0));
        lp0.y = __float2bfloat16_rn(x.y - __bfloat162float(h1));
        lp1.x = __float2bfloat16_rn(x.z - __bfloat162float(h2));
        lp1.y = __float2bfloat16_rn(x.w - __bfloat162float(h3));
        *(__nv_bfloat162*)(hi + idx) = hp0;
        *(__nv_bfloat162*)(hi + idx + 2) = hp1;
        *(__nv_bfloat162*)(lo + idx) = lp0;
        *(__nv_bfloat162*)(lo + idx + 2) = lp1;
    }
}

__global__ void transpose_convert_w(const float* __restrict__ Wq, const float* __restrict__ Wk,
                                    const float* __restrict__ Wv, const float* __restrict__ Wo) {
    __shared__ float t[32][33];
    int z = blockIdx.z;
    const float* W = (z == 0) ? Wq : (z == 1) ? Wk : (z == 2) ? Wv : Wo;
    __nv_bfloat16* whi = g_wthi + (size_t)z * W_ELEMS;
    __nv_bfloat16* wlo = g_wtlo + (size_t)z * W_ELEMS;
    int n0 = blockIdx.x * 32, k0 = blockIdx.y * 32;
    int tx = threadIdx.x, ty = threadIdx.y;
    #pragma unroll
    for (int i = 0; i < 4; i++) {
        int kr = ty + i * 8;
        t[kr][tx] = W[(size_t)(k0 + kr) * Hn + n0 + tx];
    }
    __syncthreads();
    #pragma unroll
    for (int i = 0; i < 4; i++) {
        int nr = ty + i * 8;
        float x = t[tx][nr];
        __nv_bfloat16 h = __float2bfloat16_rn(x);
        whi[(size_t)(n0 + nr) * Hn + k0 + tx] = h;
        wlo[(size_t)(n0 + nr) * Hn + k0 + tx] = __float2bfloat16_rn(x - __bfloat162float(h));
    }
}

// ---------------- mma.sync GEMM: 3-stage cp.async + frag double-buffer ----------------
#define GT_TILE 16384
#define GT_BUF  (4*GT_TILE)          // 65536 per stage
#define GT_NSTAGE 3
#define GT_SMEM_BYTES (GT_NSTAGE*GT_BUF)  // 196608
#define NCHUNK 16

__device__ __forceinline__ void gemm_ld_frags(
    uint32_t (&Ah)[4][4], uint32_t (&Al)[4][4], uint32_t (&Bh)[2][4], uint32_t (&Bl)[2][4],
    uint32_t tAhi, uint32_t tAlo, uint32_t tBhi, uint32_t tBlo, int kb,
    int wm, int wn, int rowoff_a, int kboff_a, int rowoff_b, int kboff_b)
{
    #pragma unroll
    for (int mf = 0; mf < 4; mf++) {
        int rw = wm + mf * 16 + rowoff_a;
        ldsm_x4(swz(tAhi, rw, kb + kboff_a), Ah[mf][0], Ah[mf][1], Ah[mf][2], Ah[mf][3]);
        ldsm_x4(swz(tAlo, rw, kb + kboff_a), Al[mf][0], Al[mf][1], Al[mf][2], Al[mf][3]);
    }
    #pragma unroll
    for (int g = 0; g < 2; g++) {
        int rwb = wn + g * 16 + rowoff_b;
        ldsm_x4(swz(tBhi, rwb, kb + kboff_b), Bh[g][0], Bh[g][1], Bh[g][2], Bh[g][3]);
        ldsm_x4(swz(tBlo, rwb, kb + kboff_b), Bl[g][0], Bl[g][1], Bl[g][2], Bl[g][3]);
    }
}

__device__ __forceinline__ void gemm_mmas(
    float (&acc)[4][4][4],
    uint32_t (&Ah)[4][4], uint32_t (&Al)[4][4], uint32_t (&Bh)[2][4], uint32_t (&Bl)[2][4])
{
    #pragma unroll
    for (int mf = 0; mf < 4; mf++)
        #pragma unroll
        for (int nf = 0; nf < 4; nf++)
            mma16816(acc[mf][nf], Ah[mf][0], Ah[mf][1], Ah[mf][2], Ah[mf][3],
                     Bh[nf >> 1][(nf & 1) * 2], Bh[nf >> 1][(nf & 1) * 2 + 1]);
    #pragma unroll
    for (int mf = 0; mf < 4; mf++)
        #pragma unroll
        for (int nf = 0; nf < 4; nf++)
            mma16816(acc[mf][nf], Ah[mf][0], Ah[mf][1], Ah[mf][2], Ah[mf][3],
                     Bl[nf >> 1][(nf & 1) * 2], Bl[nf >> 1][(nf & 1) * 2 + 1]);
    #pragma unroll
    for (int mf = 0; mf < 4; mf++)
        #pragma unroll
        for (int nf = 0; nf < 4; nf++)
            mma16816(acc[mf][nf], Al[mf][0], Al[mf][1], Al[mf][2], Al[mf][3],
                     Bh[nf >> 1][(nf & 1) * 2], Bh[nf >> 1][(nf & 1) * 2 + 1]);
}

template<int BF16OUT>
__device__ __forceinline__ void gemm_mma_body(
    const __nv_bfloat16* __restrict__ Ahi, const __nv_bfloat16* __restrict__ Alo,
    const __nv_bfloat16* __restrict__ Bhi, const __nv_bfloat16* __restrict__ Blo,
    const float* __restrict__ bias, float* __restrict__ C,
    __nv_bfloat16* __restrict__ Chi, __nv_bfloat16* __restrict__ Clo)
{
    extern __shared__ char smc[];
    uint32_t smb = smem_to_u32(smc);

    int tid = threadIdx.x;
    int wid = tid >> 5, lane = tid & 31;
    int r0 = blockIdx.y * 128;
    int c0 = blockIdx.x * 128;
    int wm = (wid >> 2) * 64;
    int wn = (wid & 3) * 32;

    int la = lane & 7, qa = lane >> 3;
    int rowoff_a = (qa & 1) * 8 + la;
    int kboff_a  = (qa >> 1) * 16;
    int rowoff_b = (qa >> 1) * 8 + la;
    int kboff_b  = (qa & 1) * 16;

    float acc[4][4][4];
    #pragma unroll
    for (int mf = 0; mf < 4; mf++)
        #pragma unroll
        for (int nf = 0; nf < 4; nf++)
            #pragma unroll
            for (int j = 0; j < 4; j++) acc[mf][nf][j] = 0.f;

    // issue helper (per chunk)
    auto issue_chunk = [&](uint32_t base, int kk0) {
        #pragma unroll
        for (int r = 0; r < 4; r++) {
            int idx = tid + 256 * r;
            int row = idx >> 3, c16 = idx & 7;
            uint32_t sw = swzoff(row, c16 * 16);
            size_t ga = (size_t)(r0 + row) * Hn + kk0 + c16 * 8;
            size_t gb = (size_t)(c0 + row) * Hn + kk0 + c16 * 8;
            cp_async16(base + sw,             Ahi + ga);
            cp_async16(base + GT_TILE + sw,   Alo + ga);
            cp_async16(base + 2*GT_TILE + sw, Bhi + gb);
            cp_async16(base + 3*GT_TILE + sw, Blo + gb);
        }
        CP_COMMIT();
    };

    issue_chunk(smb,          0);
    issue_chunk(smb + GT_BUF, 64);

    int st = 0;
    for (int ch = 0; ch < NCHUNK; ch++) {
        if (ch + 2 < NCHUNK) {
            int stw = st + 2; if (stw >= GT_NSTAGE) stw -= GT_NSTAGE;
            issue_chunk(smb + (uint32_t)stw * GT_BUF, (ch + 2) * 64);
            CP_WAIT2();
        } else if (ch + 1 < NCHUNK) {
            CP_WAIT1();
        } else {
            CP_WAIT0();
        }
        __syncthreads();

        uint32_t cb = smb + (uint32_t)st * GT_BUF;
        uint32_t tAhi = cb, tAlo = cb + GT_TILE, tBhi = cb + 2*GT_TILE, tBlo = cb + 3*GT_TILE;

        uint32_t Ah0[4][4], Al0[4][4], Bh0[2][4], Bl0[2][4];
        uint32_t Ah1[4][4], Al1[4][4], Bh1[2][4], Bl1[2][4];
        gemm_ld_frags(Ah0, Al0, Bh0, Bl0, tAhi, tAlo, tBhi, tBlo, 0,
                      wm, wn, rowoff_a, kboff_a, rowoff_b, kboff_b);
        gemm_ld_frags(Ah1, Al1, Bh1, Bl1, tAhi, tAlo, tBhi, tBlo, 32,
                      wm, wn, rowoff_a, kboff_a, rowoff_b, kboff_b);
        gemm_mmas(acc, Ah0, Al0, Bh0, Bl0);
        gemm_ld_frags(Ah0, Al0, Bh0, Bl0, tAhi, tAlo, tBhi, tBlo, 64,
                      wm, wn, rowoff_a, kboff_a, rowoff_b, kboff_b);
        gemm_mmas(acc, Ah1, Al1, Bh1, Bl1);
        gemm_ld_frags(Ah1, Al1, Bh1, Bl1, tAhi, tAlo, tBhi, tBlo, 96,
                      wm, wn, rowoff_a, kboff_a, rowoff_b, kboff_b);
        gemm_mmas(acc, Ah0, Al0, Bh0, Bl0);
        gemm_mmas(acc, Ah1, Al1, Bh1, Bl1);
        __syncthreads();
        if (++st == GT_NSTAGE) st = 0;
    }

    #pragma unroll
    for (int mf = 0; mf < 4; mf++) {
        int row = r0 + wm + mf * 16 + (lane >> 2);
        #pragma unroll
        for (int nf = 0; nf < 4; nf++) {
            int col = c0 + wn + nf * 8 + 2 * (lane & 3);
            float b0 = bias[col], b1 = bias[col + 1];
            float v0 = acc[mf][nf][0] + b0, v1 = acc[mf][nf][1] + b1;
            float v2 = acc[mf][nf][2] + b0, v3 = acc[mf][nf][3] + b1;
            if (BF16OUT) {
                __nv_bfloat162 h0 = __float22bfloat162_rn(make_float2(v0, v1));
                __nv_bfloat162 l0 = __float22bfloat162_rn(make_float2(
                    v0 - __bfloat162float(h0.x), v1 - __bfloat162float(h0.y)));
                __nv_bfloat162 h1 = __float22bfloat162_rn(make_float2(v2, v3));
                __nv_bfloat162 l1 = __float22bfloat162_rn(make_float2(
                    v2 - __bfloat162float(h1.x), v3 - __bfloat162float(h1.y)));
                *(__nv_bfloat162*)(Chi + (size_t)row * Hn + col)       = h0;
                *(__nv_bfloat162*)(Clo + (size_t)row * Hn + col)       = l0;
                *(__nv_bfloat162*)(Chi + (size_t)(row + 8) * Hn + col) = h1;
                *(__nv_bfloat162*)(Clo + (size_t)(row + 8) * Hn + col) = l1;
            } else {
                *(float2*)(C + (size_t)row * Hn + col)       = make_float2(v0, v1);
                *(float2*)(C + (size_t)(row + 8) * Hn + col) = make_float2(v2, v3);
            }
        }
    }
}

__global__ void __launch_bounds__(256, 1) qkv_tc(
    const float* __restrict__ bq, const float* __restrict__ bk, const float* __restrict__ bv)
{
    int z = blockIdx.z;
    const float* bias = (z == 0) ? bq : (z == 1) ? bk : bv;
    __nv_bfloat16* Chi = (z == 0) ? g_qhi : (z == 1) ? g_khi : g_vhi;
    __nv_bfloat16* Clo = (z == 0) ? g_qlo : (z == 1) ? g_klo : g_vlo;
    gemm_mma_body<1>(g_xhi, g_xlo,
                     g_wthi + (size_t)z * W_ELEMS, g_wtlo + (size_t)z * W_ELEMS,
                     bias, nullptr, Chi, Clo);
}

__global__ void __launch_bounds__(256, 1) out_tc(const float* __restrict__ bo, float* __restrict__ C)
{
    gemm_mma_body<0>(g_ohi, g_olo,
                     g_wthi + (size_t)3 * W_ELEMS, g_wtlo + (size_t)3 * W_ELEMS,
                     bo, C, nullptr, nullptr);
}

// ---------------- flash attention on mma.sync (pipelined frags, log2 softmax) ----------------
#define AT_KVBUF 32768
#define AT_SMEM (4096 + 2*AT_KVBUF)  // 69632

__device__ __forceinline__ void qk6(float* c0, float* c1, uint32_t* Q4a, uint32_t* Q4b,
                                    uint32_t* kh, uint32_t* kl) {
    // Q4a = Qh[kd], Q4b = Ql[kd]
    mma16816(c0, Q4a[0], Q4a[1], Q4a[2], Q4a[3], kh[0], kh[1]);
    mma16816(c1, Q4a[0], Q4a[1], Q4a[2], Q4a[3], kh[2], kh[3]);
    mma16816(c0, Q4a[0], Q4a[1], Q4a[2], Q4a[3], kl[0], kl[1]);
    mma16816(c1, Q4a[0], Q4a[1], Q4a[2], Q4a[3], kl[2], kl[3]);
    mma16816(c0, Q4b[0], Q4b[1], Q4b[2], Q4b[3], kh[0], kh[1]);
    mma16816(c1, Q4b[0], Q4b[1], Q4b[2], Q4b[3], kh[2], kh[3]);
}

__global__ void __launch_bounds__(256) attn_mma() {
    extern __shared__ char smc[];
    uint32_t smb = smem_to_u32(smc);
    float* colb_sm = (float*)smc;
    uint32_t bufb = smb + 4096;

    int tid = threadIdx.x;
    int wid = tid >> 5, lane = tid & 31;
    int b = blockIdx.z, h = blockIdx.y;
    int i0 = blockIdx.x * 128;

    int la = lane & 7, qa = lane >> 3;
    int roa = (qa & 1) * 8 + la, kba = (qa >> 1) * 16;   // A-style / trans-V style
    int rob = (qa >> 1) * 8 + la, kbb = (qa & 1) * 16;   // B-style (K)

    // stage colb pre-scaled by log2e
    #pragma unroll
    for (int r = 0; r < 4; r++)
        colb_sm[tid + 256 * r] = g_colb[b * Sn + tid + 256 * r] * LOG2E;

    // stage Q tile [128 x 64] hi/lo, extract to regs
    {
        const __nv_bfloat16* qhb = g_qhi + (size_t)(b * Sn + i0) * Hn + h * HDn;
        const __nv_bfloat16* qlb = g_qlo + (size_t)(b * Sn + i0) * Hn + h * HDn;
        #pragma unroll
        for (int r = 0; r < 4; r++) {
            int idx = tid + 256 * r;
            int row = idx >> 3, c16 = idx & 7;
            uint32_t sw = swzoff(row, c16 * 16);
            size_t ga = (size_t)row * Hn + c16 * 8;
            *(uint4*)(smc + 4096 + sw)         = *(const uint4*)(qhb + ga);
            *(uint4*)(smc + 4096 + 16384 + sw) = *(const uint4*)(qlb + ga);
        }
    }
    __syncthreads();
    uint32_t Qh[4][4], Ql[4][4];
    #pragma unroll
    for (int kd = 0; kd < 4; kd++) {
        int rw = wid * 16 + roa;
        ldsm_x4(swz(bufb, rw, kd * 32 + kba),         Qh[kd][0], Qh[kd][1], Qh[kd][2], Qh[kd][3]);
        ldsm_x4(swz(bufb + 16384, rw, kd * 32 + kba), Ql[kd][0], Ql[kd][1], Ql[kd][2], Ql[kd][3]);
    }
    __syncthreads();

    int r_g = i0 + wid * 16 + (lane >> 2);
    int vt0 = g_vt[b * Sn + r_g];
    int vt1 = g_vt[b * Sn + r_g + 8];

    float m0 = -3.0e38f, m1 = -3.0e38f, l0 = 0.f, l1 = 0.f;
    float acc[8][4];
    #pragma unroll
    for (int t = 0; t < 8; t++)
        #pragma unroll
        for (int j = 0; j < 4; j++) acc[t][j] = 0.f;

    const __nv_bfloat16* khb = g_khi + (size_t)b * Sn * Hn + h * HDn;
    const __nv_bfloat16* klb = g_klo + (size_t)b * Sn * Hn + h * HDn;
    const __nv_bfloat16* vhb = g_vhi + (size_t)b * Sn * Hn + h * HDn;
    const __nv_bfloat16* vlb = g_vlo + (size_t)b * Sn * Hn + h * HDn;

    auto issue_kv = [&](uint32_t base, int j0) {
        #pragma unroll
        for (int r = 0; r < 2; r++) {
            int idx = tid + 256 * r;
            int row = idx >> 3, c16 = idx & 7;
            uint32_t sw = swzoff(row, c16 * 16);
            size_t go = (size_t)(j0 + row) * Hn + c16 * 8;
            cp_async16(base + sw,         khb + go);
            cp_async16(base + 8192 + sw,  klb + go);
            cp_async16(base + 16384 + sw, vhb + go);
            cp_async16(base + 24576 + sw, vlb + go);
        }
        CP_COMMIT();
    };

    issue_kv(bufb, 0);

    for (int jt = 0; jt < Sn / 64; jt++) {
        if (jt + 1 < Sn / 64) {
            issue_kv(bufb + ((jt + 1) & 1) * AT_KVBUF, (jt + 1) * 64);
            CP_WAIT1();
        } else {
            CP_WAIT0();
        }
        __syncthreads();

        uint32_t cb = bufb + (jt & 1) * AT_KVBUF;
        uint32_t Kh = cb, Kl = cb + 8192, Vh = cb + 16384, Vl = cb + 24576;

        // S = Q K^T (3-pass hi/lo), pipelined K fragments
        float s[8][4];
        #pragma unroll
        for (int t = 0; t < 8; t++)
            #pragma unroll
            for (int j = 0; j < 4; j++) s[t][j] = 0.f;

        {
            uint32_t kh0[4], kl0[4], kh1[4], kl1[4];
            ldsm_x4(swz(Kh, 0 * 16 + rob, 0 * 32 + kbb), kh0[0], kh0[1], kh0[2], kh0[3]);
            ldsm_x4(swz(Kl, 0 * 16 + rob, 0 * 32 + kbb), kl0[0], kl0[1], kl0[2], kl0[3]);
            #pragma unroll
            for (int idx = 0; idx < 16; idx++) {
                int kd = idx >> 2, ng = idx & 3;
                int ni = idx + 1, nkd = ni >> 2, nng = ni & 3;
                if (idx & 1) {
                    if (ni < 16) {
                        ldsm_x4(swz(Kh, nng * 16 + rob, nkd * 32 + kbb), kh0[0], kh0[1], kh0[2], kh0[3]);
                        ldsm_x4(swz(Kl, nng * 16 + rob, nkd * 32 + kbb), kl0[0], kl0[1], kl0[2], kl0[3]);
                    }
                    qk6(s[2*ng], s[2*ng+1], Qh[kd], Ql[kd], kh1, kl1);
                } else {
                    if (ni < 16) {
                        ldsm_x4(swz(Kh, nng * 16 + rob, nkd * 32 + kbb), kh1[0], kh1[1], kh1[2], kh1[3]);
                        ldsm_x4(swz(Kl, nng * 16 + rob, nkd * 32 + kbb), kl1[0], kl1[1], kl1[2], kl1[3]);
                    }
                    qk6(s[2*ng], s[2*ng+1], Qh[kd], Ql[kd], kh0, kl0);
                }
            }
        }

        // scale + bias (log2 domain) + online softmax
        float rmax0 = -3.0e38f, rmax1 = -3.0e38f;
        #pragma unroll
        for (int t = 0; t < 8; t++) {
            int jc = jt * 64 + t * 8 + (lane & 3) * 2;
            float cb0 = colb_sm[jc], cb1 = colb_sm[jc + 1];
            s[t][0] = s[t][0] * SCALE_L2E + cb0 + (jc     == vt0 ? VERB_L2E : 0.f);
            s[t][1] = s[t][1] * SCALE_L2E + cb1 + (jc + 1 == vt0 ? VERB_L2E : 0.f);
            s[t][2] = s[t][2] * SCALE_L2E + cb0 + (jc     == vt1 ? VERB_L2E : 0.f);
            s[t][3] = s[t][3] * SCALE_L2E + cb1 + (jc + 1 == vt1 ? VERB_L2E : 0.f);
            rmax0 = fmaxf(rmax0, fmaxf(s[t][0], s[t][1]));
            rmax1 = fmaxf(rmax1, fmaxf(s[t][2], s[t][3]));
        }
        rmax0 = fmaxf(rmax0, __shfl_xor_sync(0xffffffffu, rmax0, 1));
        rmax0 = fmaxf(rmax0, __shfl_xor_sync(0xffffffffu, rmax0, 2));
        rmax1 = fmaxf(rmax1, __shfl_xor_sync(0xffffffffu, rmax1, 1));
        rmax1 = fmaxf(rmax1, __shfl_xor_sync(0xffffffffu, rmax1, 2));
        float mn0 = fmaxf(m0, rmax0), mn1 = fmaxf(m1, rmax1);
        float cr0 = ex2f(m0 - mn0), cr1 = ex2f(m1 - mn1);
        m0 = mn0; m1 = mn1;

        float sum0 = 0.f, sum1 = 0.f;
        uint32_t Ph[4][4], Pl[4][4];
        #pragma unroll
        for (int g = 0; g < 4; g++) {
            #pragma unroll
            for (int hh = 0; hh < 2; hh++) {
                int t = 2 * g + hh;
                float p0 = ex2f(s[t][0] - mn0);
                float p1 = ex2f(s[t][1] - mn0);
                float p2 = ex2f(s[t][2] - mn1);
                float p3 = ex2f(s[t][3] - mn1);
                sum0 += p0 + p1; sum1 += p2 + p3;
                uint32_t h01 = pack_bf16(p0, p1);
                uint32_t h23 = pack_bf16(p2, p3);
                __nv_bfloat162 hh01 = *(__nv_bfloat162*)&h01;
                __nv_bfloat162 hh23 = *(__nv_bfloat162*)&h23;
                uint32_t l01 = pack_bf16(p0 - __bfloat162float(hh01.x), p1 - __bfloat162float(hh01.y));
                uint32_t l23 = pack_bf16(p2 - __bfloat162float(hh23.x), p3 - __bfloat162float(hh23.y));
                Ph[g][hh * 2]     = h01;
                Ph[g][hh * 2 + 1] = h23;
                Pl[g][hh * 2]     = l01;
                Pl[g][hh * 2 + 1] = l23;
            }
        }
        sum0 += __shfl_xor_sync(0xffffffffu, sum0, 1);
        sum0 += __shfl_xor_sync(0xffffffffu, sum0, 2);
        sum1 += __shfl_xor_sync(0xffffffffu, sum1, 1);
        sum1 += __shfl_xor_sync(0xffffffffu, sum1, 2);
        l0 = l0 * cr0 + sum0;
        l1 = l1 * cr1 + sum1;
        #pragma unroll
        for (int t = 0; t < 8; t++) {
            acc[t][0] *= cr0; acc[t][1] *= cr0;
            acc[t][2] *= cr1; acc[t][3] *= cr1;
        }

        // O += P V (3-pass), pipelined V fragments (trans loads)
        {
            uint32_t vh0[4], vl0[4], vh1[4], vl1[4];
            ldsm_x4_t(swz(Vh, 0 * 16 + roa, 0 * 32 + kba), vh0[0], vh0[1], vh0[2], vh0[3]);
            ldsm_x4_t(swz(Vl, 0 * 16 + roa, 0 * 32 + kba), vl0[0], vl0[1], vl0[2], vl0[3]);
            #pragma unroll
            for (int idx = 0; idx < 16; idx++) {
                int g = idx >> 2, gd = idx & 3;
                int ni = idx + 1, ngp = ni >> 2, ngd = ni & 3;
                uint32_t *vhc, *vlc;
                if (idx & 1) {
                    if (ni < 16) {
                        ldsm_x4_t(swz(Vh, ngp * 16 + roa, ngd * 32 + kba), vh0[0], vh0[1], vh0[2], vh0[3]);
                        ldsm_x4_t(swz(Vl, ngp * 16 + roa, ngd * 32 + kba), vl0[0], vl0[1], vl0[2], vl0[3]);
                    }
                    vhc = vh1; vlc = vl1;
                } else {
                    if (ni < 16) {
                        ldsm_x4_t(swz(Vh, ngp * 16 + roa, ngd * 32 + kba), vh1[0], vh1[1], vh1[2], vh1[3]);
                        ldsm_x4_t(swz(Vl, ngp * 16 + roa, ngd * 32 + kba), vl1[0], vl1[1], vl1[2], vl1[3]);
                    }
                    vhc = vh0; vlc = vl0;
                }
                float* c0 = acc[2*gd];
                float* c1 = acc[2*gd+1];
                mma16816(c0, Ph[g][0], Ph[g][1], Ph[g][2], Ph[g][3], vhc[0], vhc[1]);
                mma16816(c1, Ph[g][0], Ph[g][1], Ph[g][2], Ph[g][3], vhc[2], vhc[3]);
                mma16816(c0, Ph[g][0], Ph[g][1], Ph[g][2], Ph[g][3], vlc[0], vlc[1]);
                mma16816(c1, Ph[g][0], Ph[g][1], Ph[g][2], Ph[g][3], vlc[2], vlc[3]);
                mma16816(c0, Pl[g][0], Pl[g][1], Pl[g][2], Pl[g][3], vhc[0], vhc[1]);
                mma16816(c1, Pl[g][0], Pl[g][1], Pl[g][2], Pl[g][3], vhc[2], vhc[3]);
            }
        }
        __syncthreads();
    }

    // epilogue: normalize, split hi/lo, store
    float inv0 = 1.f / l0, inv1 = 1.f / l1;
    __nv_bfloat16* ohb = g_ohi + (size_t)(b * Sn + r_g) * Hn + h * HDn;
    __nv_bfloat16* olb = g_olo + (size_t)(b * Sn + r_g) * Hn + h * HDn;
    #pragma unroll
    for (int t = 0; t < 8; t++) {
        int d = t * 8 + (lane & 3) * 2;
        float v0 = acc[t][0] * inv0, v1 = acc[t][1] * inv0;
        float v2 = acc[t][2] * inv1, v3 = acc[t][3] * inv1;
        __nv_bfloat162 h0 = __float22bfloat162_rn(make_float2(v0, v1));
        __nv_bfloat162 l0v = __float22bfloat162_rn(make_float2(
            v0 - __bfloat162float(h0.x), v1 - __bfloat162float(h0.y)));
        __nv_bfloat162 h1 = __float22bfloat162_rn(make_float2(v2, v3));
        __nv_bfloat162 l1v = __float22bfloat162_rn(make_float2(
            v2 - __bfloat162float(h1.x), v3 - __bfloat162float(h1.y)));
        *(__nv_bfloat162*)(ohb + d)                  = h0;
        *(__nv_bfloat162*)(olb + d)                  = l0v;
        *(__nv_bfloat162*)(ohb + (size_t)8 * Hn + d) = h1;
        *(__nv_bfloat162*)(olb + (size_t)8 * Hn + d) = l1v;
    }
}

// ---------------- launch ----------------
extern "C" void kernel_launch(void* const* d_in, const int* in_sizes, int n_in,
                              void* d_out, int out_size) {
    const float* hidden = (const float*)d_in[0];
    const int*   morpho = (const int*)d_in[1];
    const float* Wq = (const float*)d_in[2];
    const float* bq = (const float*)d_in[3];
    const float* Wk = (const float*)d_in[4];
    const float* bk = (const float*)d_in[5];
    const float* Wv = (const float*)d_in[6];
    const float* bv = (const float*)d_in[7];
    const float* Wo = (const float*)d_in[8];
    const float* bo = (const float*)d_in[9];
    float* out = (float*)d_out;

    cudaFuncSetAttribute(qkv_tc,
                         cudaFuncAttributeMaxDynamicSharedMemorySize, GT_SMEM_BYTES);
    cudaFuncSetAttribute(out_tc,
                         cudaFuncAttributeMaxDynamicSharedMemorySize, GT_SMEM_BYTES);
    cudaFuncSetAttribute(attn_mma,
                         cudaFuncAttributeMaxDynamicSharedMemorySize, AT_SMEM);

    static __nv_bfloat16 *xhi_p = nullptr, *xlo_p = nullptr;
    if (!xhi_p) {
        cudaGetSymbolAddress((void**)&xhi_p, g_xhi);
        cudaGetSymbolAddress((void**)&xlo_p, g_xlo);
    }

    morpho_kernel<<<Bn, Sn>>>(morpho);
    convert_split<<<(Mtot*Hn/4 + 255) / 256, 256>>>(hidden, xhi_p, xlo_p, Mtot*Hn);
    transpose_convert_w<<<dim3(32, 32, 4), dim3(32, 8)>>>(Wq, Wk, Wv, Wo);
    qkv_tc<<<dim3(Hn/128, Mtot/128, 3), 256, GT_SMEM_BYTES>>>(bq, bk, bv);
    attn_mma<<<dim3(Sn/128, NHn, Bn), 256, AT_SMEM>>>();
    out_tc<<<dim3(Hn/128, Mtot/128, 1), 256, GT_SMEM_BYTES>>>(bo, out);
}